// round 7
// baseline (speedup 1.0000x reference)
#include <cuda_runtime.h>
#include <cuda_bf16.h>

#define T_STEPS 2048
#define IN_DIM  118
#define EMB     128
#define H       1536
#define H4      6144
#define H2      1024
#define OUTD    128
#define NBLK    128
#define NTHR    1024   // 16 critical (C) warps + 16 prefetch (P) warps
#define RW      768    // packed words per 1536-col row
#define DSMB    (48*RW*4 + 48*128*4 + 12*128*4)   // 178176 bytes dynamic SMEM

// ---------------- device-global scratch ----------------------------------------------
__device__ __align__(128) unsigned g_WI1[(size_t)H4 * RW];   // W_ih1 packed rows (18.9MB)
__device__ __align__(128) unsigned g_WH0[(size_t)H4 * RW];   // W_hh0
__device__ __align__(128) unsigned g_WH1[(size_t)H4 * RW];   // W_hh1
__device__ __align__(128) unsigned g_WX [(size_t)H4 * 128];  // W_ih0 x/emb part (3MB)
__device__ __align__(128) float g_WCBT[(size_t)H * OUTD];    // (W_out@W_hl)^T  [c][r]
__device__ __align__(128) unsigned g_WMp[EMB * OUTD / 2];    // W_map bf16 pairs
__device__ float g_bcomb[OUTD];
__device__ __align__(16) float g_h0v[H];
__device__ __align__(16) float g_h1v[H];
__device__ float g_L[2][OUTD];               // double-buffered logit accumulators
__device__ unsigned g_flag[NBLK];            // per-block barrier flags (epoch values)
__device__ unsigned g_done = 0;

// ---------------- bf16-pair packing with hi-compensation ------------------------------
__device__ __forceinline__ unsigned pack2(float wlo, float whi) {
    unsigned lo16 = (unsigned)__bfloat16_as_ushort(__float2bfloat16(wlo));
    unsigned base = __float_as_uint(whi) & 0xffff0000u;
    unsigned c0 = base | lo16, c1 = (base + 0x10000u) | lo16, c2 = (base - 0x10000u) | lo16;
    float d0 = fabsf(__uint_as_float(c0) - whi);
    float d1 = fabsf(__uint_as_float(c1) - whi);
    float d2 = fabsf(__uint_as_float(c2) - whi);
    unsigned best = c0; float bd = d0;
    if (d1 < bd) { bd = d1; best = c1; }
    if (d2 < bd) { best = c2; }
    return best;
}

__global__ void pack_all(const float* __restrict__ Wih0, const float* __restrict__ Whh0,
                         const float* __restrict__ Wih1, const float* __restrict__ Whh1,
                         const float* __restrict__ Whl,  const float* __restrict__ Wout,
                         const float* __restrict__ bhl,  const float* __restrict__ bout,
                         const float* __restrict__ Wmap) {
    const size_t nR  = (size_t)H4 * RW;
    const size_t nX  = (size_t)H4 * 128;
    const size_t nCT = (size_t)H * OUTD;
    const size_t nM  = (size_t)EMB * OUTD / 2;
    const size_t total = 3 * nR + nX + nCT + nM + OUTD;
    size_t stride = (size_t)gridDim.x * blockDim.x;
    for (size_t i = (size_t)blockIdx.x * blockDim.x + threadIdx.x; i < total; i += stride) {
        if (i < 3 * nR) {
            int m = (int)(i / nR);
            size_t k = i - (size_t)m * nR;
            size_t r = k / RW;
            int c = 2 * (int)(k % RW);
            const float* M = (m == 0) ? Wih1 : (m == 1) ? Whh0 : Whh1;
            unsigned* D = (m == 0) ? g_WI1 : (m == 1) ? g_WH0 : g_WH1;
            D[k] = pack2(M[r * H + c], M[r * H + c + 1]);
        } else if (i < 3 * nR + nX) {
            size_t k = i - 3 * nR;
            size_t r = k / 128;
            int c = 2 * (int)(k % 128);
            float lo = (c < IN_DIM + EMB)     ? Wih0[r * 246 + c]     : 0.f;
            float hi = (c + 1 < IN_DIM + EMB) ? Wih0[r * 246 + c + 1] : 0.f;
            g_WX[k] = pack2(lo, hi);
        } else if (i < 3 * nR + nX + nCT) {
            size_t k = i - 3 * nR - nX;
            int c = (int)(k / OUTD), r = (int)(k % OUTD);
            float s = 0.f;
            #pragma unroll 4
            for (int kk = 0; kk < H2; kk++)
                s = fmaf(__ldg(Wout + r * H2 + kk), __ldg(Whl + (size_t)kk * H + c), s);
            g_WCBT[k] = s;
        } else if (i < 3 * nR + nX + nCT + nM) {
            size_t k = i - 3 * nR - nX - nCT;
            int r = (int)(k / (OUTD / 2)), q = (int)(k % (OUTD / 2));
            g_WMp[k] = pack2(Wmap[r * OUTD + 2 * q], Wmap[r * OUTD + 2 * q + 1]);
        } else {
            int r = (int)(i - 3 * nR - nX - nCT - nM);
            float s = 0.f;
            #pragma unroll 4
            for (int kk = 0; kk < H2; kk++) s = fmaf(Wout[r * H2 + kk], bhl[kk], s);
            float bc = s + bout[r];
            g_bcomb[r] = bc;
            g_L[0][r] = bc; g_L[1][r] = bc;
        }
    }
}

// ---------------- core math -----------------------------------------------------------
__device__ __forceinline__ float wred(float a) {
    a += __shfl_xor_sync(0xffffffffu, a, 16);
    a += __shfl_xor_sync(0xffffffffu, a, 8);
    a += __shfl_xor_sync(0xffffffffu, a, 4);
    a += __shfl_xor_sync(0xffffffffu, a, 2);
    a += __shfl_xor_sync(0xffffffffu, a, 1);
    return a;
}
__device__ __forceinline__ float sigmoidf_(float x) { return 1.f / (1.f + expf(-x)); }

// f32x2 FMA with b64-held accumulator and prepacked x pair. [SHL + pack + FFMA2]
__device__ __forceinline__ void bffma2p(unsigned long long& acc, unsigned w,
                                        unsigned long long xp) {
    asm("{\n\t"
        ".reg .b32 lo;\n\t"
        ".reg .b64 wp;\n\t"
        "shl.b32 lo, %1, 16;\n\t"
        "mov.b64 wp, {lo, %1};\n\t"
        "fma.rn.f32x2 %0, wp, %2, %0;\n\t"
        "}" : "+l"(acc) : "r"(w), "l"(xp));
}
__device__ __forceinline__ float upsum(unsigned long long a) {
    return __uint_as_float((unsigned)a) + __uint_as_float((unsigned)(a >> 32));
}

// 3-row x 8-col micro-step on packed words
#define MAC3(W0, W1, W2, XA, XB)                                     \
    do {                                                             \
        bffma2p(A0, (W0).x, (XA).x); bffma2p(A0, (W0).y, (XA).y);    \
        bffma2p(A0, (W0).z, (XB).x); bffma2p(A0, (W0).w, (XB).y);    \
        bffma2p(A1, (W1).x, (XA).x); bffma2p(A1, (W1).y, (XA).y);    \
        bffma2p(A1, (W1).z, (XB).x); bffma2p(A1, (W1).w, (XB).y);    \
        bffma2p(A2, (W2).x, (XA).x); bffma2p(A2, (W2).y, (XA).y);    \
        bffma2p(A2, (W2).z, (XB).x); bffma2p(A2, (W2).w, (XB).y);    \
    } while (0)

// 3-row dot, weights in SMEM (rows are 768-word consecutive at base sw + li*RW)
__device__ __forceinline__ void dot3_smem(const unsigned* __restrict__ sw, int i0,
                                          const float* __restrict__ sx, int lane,
                                          float& s0, float& s1, float& s2) {
    unsigned long long A0 = 0ull, A1 = 0ull, A2 = 0ull;
    const unsigned* w0 = sw + i0 * RW + lane * 4;
    #pragma unroll 2
    for (int it = 0; it < 6; ++it) {
        ulonglong2 xa = *reinterpret_cast<const ulonglong2*>(sx + it * 256 + lane * 8);
        ulonglong2 xb = *reinterpret_cast<const ulonglong2*>(sx + it * 256 + lane * 8 + 4);
        uint4 v0 = *reinterpret_cast<const uint4*>(w0 + it * 128);
        uint4 v1 = *reinterpret_cast<const uint4*>(w0 + RW + it * 128);
        uint4 v2 = *reinterpret_cast<const uint4*>(w0 + 2 * RW + it * 128);
        MAC3(v0, v1, v2, xa, xb);
    }
    s0 = wred(upsum(A0)); s1 = wred(upsum(A1)); s2 = wred(upsum(A2));
}

// 3-row dot, weights from global (L2 stream)
__device__ __forceinline__ void dot3_glob(const unsigned* __restrict__ w0,
                                          const unsigned* __restrict__ w1,
                                          const unsigned* __restrict__ w2,
                                          const float* __restrict__ sx, int lane,
                                          float& s0, float& s1, float& s2) {
    unsigned long long A0 = 0ull, A1 = 0ull, A2 = 0ull;
    #pragma unroll 2
    for (int it = 0; it < 6; ++it) {
        ulonglong2 xa = *reinterpret_cast<const ulonglong2*>(sx + it * 256 + lane * 8);
        ulonglong2 xb = *reinterpret_cast<const ulonglong2*>(sx + it * 256 + lane * 8 + 4);
        uint4 v0 = __ldcg(reinterpret_cast<const uint4*>(w0 + it * 128 + lane * 4));
        uint4 v1 = __ldcg(reinterpret_cast<const uint4*>(w1 + it * 128 + lane * 4));
        uint4 v2 = __ldcg(reinterpret_cast<const uint4*>(w2 + it * 128 + lane * 4));
        MAC3(v0, v1, v2, xa, xb);
    }
    s0 = wred(upsum(A0)); s1 = wred(upsum(A1)); s2 = wred(upsum(A2));
}

#define BARC() asm volatile("bar.sync 1, 512;" ::: "memory")
#define BARP() asm volatile("bar.sync 2, 512;" ::: "memory")

__device__ __forceinline__ void flag_arrive(int bid, unsigned ep) {
    asm volatile("st.release.gpu.global.u32 [%0], %1;"
                 :: "l"(&g_flag[bid]), "r"(ep) : "memory");
}
__device__ __forceinline__ void flag_poll(int slot, unsigned ep) {
    unsigned v;
    do {
        asm volatile("ld.acquire.gpu.global.u32 %0, [%1];"
                     : "=r"(v) : "l"(&g_flag[slot]) : "memory");
    } while (v < ep);
}

// ---------------- persistent main kernel ----------------------------------------------
__global__ void __launch_bounds__(NTHR, 1) lstm_main(
    const float* __restrict__ inputVecs,
    const float* __restrict__ h0in, const float* __restrict__ c0in,
    const float* __restrict__ bi0, const float* __restrict__ bh0,
    const float* __restrict__ bi1, const float* __restrict__ bh1,
    const float* __restrict__ bm,
    float* __restrict__ out) {
    extern __shared__ __align__(16) unsigned dsm[];
    unsigned* sWI = dsm;                        // 48*768 words (ih1 slice)
    unsigned* sWX = dsm + 48 * RW;              // 48*128 words (x/emb slice)
    float* sWC = (float*)(dsm + 48 * RW + 48 * 128);   // 12*128 (logit slice)

    __shared__ __align__(16) float sxh[H];      // C gather of h0n
    __shared__ __align__(16) float spxh0[H];    // P gather of h0n
    __shared__ __align__(16) float spxh1[H];    // P gather of h1n
    __shared__ __align__(16) float sxx[256];
    __shared__ float sh1[12];
    __shared__ float sgate[48], sg1[48];
    __shared__ float pArow[48], pBrow[48];
    __shared__ float bA[48], bB[48];
    __shared__ float sy[OUTD], semb[EMB], sbm[EMB];

    const int tid = threadIdx.x, lane = tid & 31, bid = blockIdx.x;
    const bool isC = tid < 512;
    const int wid = tid >> 5;          // C: 0..15
    const int i0 = (wid & 15) * 3;     // local row base for this warp's 3 rows

    // prologue: copy this block's step-invariant weight slices to SMEM
    for (int i = tid; i < 48 * RW; i += NTHR) {
        int li = i / RW, w = i - li * RW;
        size_t r = (size_t)(li / 12) * H + bid * 12 + (li % 12);
        sWI[i] = g_WI1[r * RW + w];
    }
    for (int i = tid; i < 48 * 128; i += NTHR) {
        int li = i >> 7, w = i & 127;
        size_t r = (size_t)(li / 12) * H + bid * 12 + (li % 12);
        sWX[i] = g_WX[r * 128 + w];
    }
    for (int i = tid; i < 12 * 128; i += NTHR)
        sWC[i] = g_WCBT[(size_t)(bid * 12 + (i >> 7)) * OUTD + (i & 127)];
    if (tid < 48) {
        int grow = (tid / 12) * H + bid * 12 + (tid % 12);
        bA[tid] = bi0[grow] + bh0[grow];
        bB[tid] = bi1[grow] + bh1[grow];
    }
    float cA = 0.f, cB = 0.f;
    if (isC && wid == 0 && lane < 12) {
        int j = bid * 12 + lane;
        cA = c0in[j]; cB = c0in[H + j];
    }
    if (isC) for (int i = tid; i < EMB; i += 512) { semb[i] = 0.f; sbm[i] = __ldg(bm + i); }
    // P prologue: initial h into SMEM for initial partials
    if (!isC) for (int i = tid - 512; i < H; i += 512) {
        spxh0[i] = __ldg(h0in + i);
        spxh1[i] = __ldg(h0in + H + i);
    }
    __syncthreads();

    // P row pointers (global streams)
    const int pw = wid & 15;
    const unsigned *wh0[3], *wh1[3];
    #pragma unroll
    for (int i = 0; i < 3; i++) {
        int idx = pw * 3 + i;
        size_t r = (size_t)(idx / 12) * H + bid * 12 + (idx % 12);
        wh0[i] = g_WH0 + r * RW;
        wh1[i] = g_WH1 + r * RW;
    }

    if (!isC) {   // initial hh partials from h0in
        float s0, s1, s2;
        dot3_glob(wh0[0], wh0[1], wh0[2], spxh0, lane, s0, s1, s2);
        if (lane == 0) { pArow[i0] = s0; pArow[i0 + 1] = s1; pArow[i0 + 2] = s2; }
        dot3_glob(wh1[0], wh1[1], wh1[2], spxh1, lane, s0, s1, s2);
        if (lane == 0) { pBrow[i0] = s0; pBrow[i0 + 1] = s1; pBrow[i0 + 2] = s2; }
    }
    __syncthreads();

    for (int t = 0; t < T_STEPS; ++t) {
        const int par = t & 1;
        const unsigned ep1 = 2 * t + 1, ep2 = 2 * t + 2;
        __syncthreads();   // step top: pArow/pBrow/semb handoff visible

        if (isC) {
            // ---- phase A (block-local): x/emb dot + pArow -> h0n --------------------
            if (tid < 256) {
                float v = 0.f;
                if (tid < IN_DIM)            v = __ldg(inputVecs + (size_t)t * IN_DIM + tid);
                else if (tid < IN_DIM + EMB) v = semb[tid - IN_DIM];
                sxx[tid] = v;
            }
            BARC();
            {
                unsigned long long A0 = 0ull, A1 = 0ull, A2 = 0ull;
                ulonglong2 xa = *reinterpret_cast<const ulonglong2*>(sxx + lane * 8);
                ulonglong2 xb = *reinterpret_cast<const ulonglong2*>(sxx + lane * 8 + 4);
                const unsigned* w0 = sWX + i0 * 128 + lane * 4;
                uint4 v0 = *reinterpret_cast<const uint4*>(w0);
                uint4 v1 = *reinterpret_cast<const uint4*>(w0 + 128);
                uint4 v2 = *reinterpret_cast<const uint4*>(w0 + 256);
                MAC3(v0, v1, v2, xa, xb);
                float s0 = wred(upsum(A0)), s1 = wred(upsum(A1)), s2 = wred(upsum(A2));
                if (lane == 0) {
                    sgate[i0]     = s0 + pArow[i0]     + bA[i0];
                    sgate[i0 + 1] = s1 + pArow[i0 + 1] + bA[i0 + 1];
                    sgate[i0 + 2] = s2 + pArow[i0 + 2] + bA[i0 + 2];
                }
            }
            BARC();
            if (wid == 0) {
                if (lane < 12) {
                    float gi = sigmoidf_(sgate[lane]);
                    float gf = sigmoidf_(sgate[12 + lane]);
                    float gg = tanhf    (sgate[24 + lane]);
                    float go = sigmoidf_(sgate[36 + lane]);
                    cA = gf * cA + gi * gg;
                    g_h0v[bid * 12 + lane] = go * tanhf(cA);
                }
                __syncwarp();
                if (lane == 0) flag_arrive(bid, ep1);            // bar1 arrive (early)
            }
            if (tid < NBLK) flag_poll(tid, ep1);                 // bar1 wait
            BARC();
            // ---- slot B: gather h0n + SMEM ih1 dot + pBrow -> h1n, logit push -------
            if (tid < 384)
                reinterpret_cast<float4*>(sxh)[tid] =
                    __ldcg(reinterpret_cast<const float4*>(g_h0v) + tid);
            BARC();
            {
                float s0, s1, s2;
                dot3_smem(sWI, i0, sxh, lane, s0, s1, s2);
                if (lane == 0) {
                    sg1[i0]     = s0 + pBrow[i0]     + bB[i0];
                    sg1[i0 + 1] = s1 + pBrow[i0 + 1] + bB[i0 + 1];
                    sg1[i0 + 2] = s2 + pBrow[i0 + 2] + bB[i0 + 2];
                }
            }
            BARC();
            if (wid == 0 && lane < 12) {
                float gi = sigmoidf_(sg1[lane]);
                float gf = sigmoidf_(sg1[12 + lane]);
                float gg = tanhf    (sg1[24 + lane]);
                float go = sigmoidf_(sg1[36 + lane]);
                cB = gf * cB + gi * gg;
                float h1n = go * tanhf(cB);
                g_h1v[bid * 12 + lane] = h1n;
                sh1[lane] = h1n;
            }
            BARC();
            if (tid < OUTD) {   // rank-12 logit contribution (SMEM weights)
                float p = 0.f;
                #pragma unroll
                for (int i = 0; i < 12; i++) p = fmaf(sWC[i * 128 + tid], sh1[i], p);
                asm volatile("red.relaxed.gpu.global.add.f32 [%0], %1;"
                             :: "l"(&g_L[par][tid]), "f"(p) : "memory");
            }
            BARC();
            if (tid == 0) flag_arrive(bid, ep2);                 // bar2 arrive
            if (tid < NBLK) flag_poll(tid, ep2);                 // bar2 wait
            BARC();
            // ---- slot4 (block-local): softmax + emb ---------------------------------
            if (tid < OUTD) sy[tid] = __ldcg(&g_L[par][tid]);
            if (tid == 256) g_L[par ^ 1][bid] = __ldg(&g_bcomb[bid]);  // reset for t+2
            BARC();
            if (wid == 0) {
                float v0 = sy[lane], v1 = sy[lane + 32], v2 = sy[lane + 64], v3 = sy[lane + 96];
                float m = fmaxf(fmaxf(v0, v1), fmaxf(v2, v3));
                #pragma unroll
                for (int o = 16; o; o >>= 1) m = fmaxf(m, __shfl_xor_sync(0xffffffffu, m, o));
                float e0 = expf(v0 - m), e1 = expf(v1 - m), e2 = expf(v2 - m), e3 = expf(v3 - m);
                float s = wred(e0 + e1 + e2 + e3);
                float inv = 1.f / s;
                e0 *= inv; e1 *= inv; e2 *= inv; e3 *= inv;
                sy[lane] = e0; sy[lane + 32] = e1; sy[lane + 64] = e2; sy[lane + 96] = e3;
                if (bid == 0) {
                    float* op = out + (size_t)t * OUTD;
                    op[lane] = e0; op[lane + 32] = e1; op[lane + 64] = e2; op[lane + 96] = e3;
                }
            }
            BARC();
            {   // emb = Wmap @ y + bm
                float xa = sy[lane * 4], xb = sy[lane * 4 + 1];
                float xc = sy[lane * 4 + 2], xd = sy[lane * 4 + 3];
                #pragma unroll
                for (int q = 0; q < 8; q++) {
                    int r = wid * 8 + q;
                    const unsigned* wm = g_WMp + r * (OUTD / 2) + lane * 2;
                    float a0 = 0.f, a1 = 0.f;
                    unsigned w0 = __ldg(wm), w1 = __ldg(wm + 1);
                    a0 = fmaf(__uint_as_float(w0 << 16), xa, a0);
                    a0 = fmaf(__uint_as_float(w0 & 0xffff0000u) , xb, a0);  // hi approx
                    a1 = fmaf(__uint_as_float(w1 << 16), xc, a1);
                    a1 = fmaf(__uint_as_float(w1 & 0xffff0000u), xd, a1);
                    float s = wred(a0 + a1);
                    if (lane == 0) semb[r] = s + sbm[r];
                }
            }
        } else {
            // ============== P-group: hh prefetch for step t+1 ========================
            const int ptid = tid - 512;
            if (ptid == 0) flag_poll(bid, 0);   // no-op keep structure (flags monotone)
            if (ptid < NBLK) flag_poll(ptid, ep1);
            BARP();
            if (ptid < 384)
                reinterpret_cast<float4*>(spxh0)[ptid] =
                    __ldcg(reinterpret_cast<const float4*>(g_h0v) + ptid);
            BARP();
            {
                float s0, s1, s2;
                dot3_glob(wh0[0], wh0[1], wh0[2], spxh0, lane, s0, s1, s2);
                if (lane == 0) { pArow[i0] = s0; pArow[i0 + 1] = s1; pArow[i0 + 2] = s2; }
            }
            if (ptid < NBLK) flag_poll(ptid, ep2);
            BARP();
            if (ptid < 384)
                reinterpret_cast<float4*>(spxh1)[ptid] =
                    __ldcg(reinterpret_cast<const float4*>(g_h1v) + ptid);
            BARP();
            {
                float s0, s1, s2;
                dot3_glob(wh1[0], wh1[1], wh1[2], spxh1, lane, s0, s1, s2);
                if (lane == 0) { pBrow[i0] = s0; pBrow[i0 + 1] = s1; pBrow[i0 + 2] = s2; }
            }
        }
    }

    // end-of-launch reset (last arriver) for graph replay
    __syncthreads();
    if (tid == 0) {
        __threadfence();
        if (atomicAdd(&g_done, 1u) == NBLK - 1) {
            for (int i = 0; i < NBLK; i++) g_flag[i] = 0u;
            g_done = 0u;
            __threadfence();
        }
    }
}

// ---------------- launch --------------------------------------------------------------
extern "C" void kernel_launch(void* const* d_in, const int* in_sizes, int n_in,
                              void* d_out, int out_size) {
    const float* inputVecs = (const float*)d_in[0];
    const float* h0    = (const float*)d_in[1];
    const float* c0    = (const float*)d_in[2];
    const float* W_ih0 = (const float*)d_in[3];
    const float* W_hh0 = (const float*)d_in[4];
    const float* b_ih0 = (const float*)d_in[5];
    const float* b_hh0 = (const float*)d_in[6];
    const float* W_ih1 = (const float*)d_in[7];
    const float* W_hh1 = (const float*)d_in[8];
    const float* b_ih1 = (const float*)d_in[9];
    const float* b_hh1 = (const float*)d_in[10];
    const float* W_hl  = (const float*)d_in[11];
    const float* b_hl  = (const float*)d_in[12];
    const float* W_out = (const float*)d_in[13];
    const float* b_out = (const float*)d_in[14];
    const float* W_map = (const float*)d_in[15];
    const float* b_map = (const float*)d_in[16];

    cudaFuncSetAttribute(lstm_main, cudaFuncAttributeMaxDynamicSharedMemorySize, DSMB);
    pack_all<<<2048, 256>>>(W_ih0, W_hh0, W_ih1, W_hh1, W_hl, W_out, b_hl, b_out, W_map);
    lstm_main<<<NBLK, NTHR, DSMB>>>(inputVecs, h0, c0,
                                    b_ih0, b_hh0, b_ih1, b_hh1,
                                    b_map, (float*)d_out);
}

// round 8
// speedup vs baseline: 2.4876x; 2.4876x over previous
#include <cuda_runtime.h>
#include <cuda_bf16.h>

#define T_STEPS 2048
#define IN_DIM  118
#define EMB     128
#define H       1536
#define H4      6144
#define H2      1024
#define OUTD    128
#define QW      384    // int8 words per 1536-col row
#define NBLK    128
#define NTHR    1024   // 16 critical (C) warps + 16 prefetch (P) warps

// ---------------- device-global scratch ----------------------------------------------
__device__ __align__(128) unsigned g_QI1[(size_t)H4 * QW];  // W_ih1 int8 rows (9.4MB)
__device__ __align__(128) unsigned g_QH0[(size_t)H4 * QW];  // W_hh0
__device__ __align__(128) unsigned g_QH1[(size_t)H4 * QW];  // W_hh1
__device__ float g_sI1[H4], g_sH0[H4], g_sH1[H4];           // per-row scales
__device__ __align__(128) unsigned g_WXp[(size_t)H4 * 128]; // W_ih0 x/emb bf16 pairs (3MB)
__device__ __align__(128) float g_WCBT[(size_t)H * OUTD];   // (W_out@W_hl)^T  [c][r]
__device__ __align__(128) unsigned g_WMp[EMB * OUTD / 2];   // W_map bf16 pairs
__device__ float g_bcomb[OUTD];
__device__ __align__(16) float g_h0v[H];
__device__ __align__(16) float g_h1v[H];
__device__ float g_L[2][OUTD];
__device__ unsigned g_count = 0;
__device__ unsigned g_done  = 0;

// ---------------- packing -------------------------------------------------------------
__device__ __forceinline__ unsigned pack2(float wlo, float whi) {
    unsigned lo16 = (unsigned)__bfloat16_as_ushort(__float2bfloat16(wlo));
    unsigned base = __float_as_uint(whi) & 0xffff0000u;
    unsigned c0 = base | lo16, c1 = (base + 0x10000u) | lo16, c2 = (base - 0x10000u) | lo16;
    float d0 = fabsf(__uint_as_float(c0) - whi);
    float d1 = fabsf(__uint_as_float(c1) - whi);
    float d2 = fabsf(__uint_as_float(c2) - whi);
    unsigned best = c0; float bd = d0;
    if (d1 < bd) { bd = d1; best = c1; }
    if (d2 < bd) { best = c2; }
    return best;
}

// one warp per row: int8 row quantization of the three big matrices
__global__ void pack_quant(const float* __restrict__ Wih1, const float* __restrict__ Whh0,
                           const float* __restrict__ Whh1) {
    int gw = blockIdx.x * (blockDim.x >> 5) + (threadIdx.x >> 5);
    int lane = threadIdx.x & 31;
    if (gw >= 3 * H4) return;
    int m = gw / H4, r = gw % H4;
    const float* M = (m == 0) ? Wih1 : (m == 1) ? Whh0 : Whh1;
    unsigned* D = (m == 0) ? g_QI1 : (m == 1) ? g_QH0 : g_QH1;
    float* S = (m == 0) ? g_sI1 : (m == 1) ? g_sH0 : g_sH1;
    const float* row = M + (size_t)r * H;
    float v[48];
    float mx = 0.f;
    #pragma unroll
    for (int i = 0; i < 48; i++) { v[i] = row[lane * 48 + i]; mx = fmaxf(mx, fabsf(v[i])); }
    #pragma unroll
    for (int o = 16; o; o >>= 1) mx = fmaxf(mx, __shfl_xor_sync(0xffffffffu, mx, o));
    float inv = (mx > 0.f) ? 127.f / mx : 0.f;
    unsigned* drow = D + (size_t)r * QW + lane * 12;
    #pragma unroll
    for (int w = 0; w < 12; w++) {
        int q0 = __float2int_rn(v[4 * w] * inv);
        int q1 = __float2int_rn(v[4 * w + 1] * inv);
        int q2 = __float2int_rn(v[4 * w + 2] * inv);
        int q3 = __float2int_rn(v[4 * w + 3] * inv);
        drow[w] = (q0 & 255) | ((q1 & 255) << 8) | ((q2 & 255) << 16) | ((q3 & 255) << 24);
    }
    if (lane == 0) S[r] = mx / 127.f;
}

__global__ void pack_rest(const float* __restrict__ Wih0, const float* __restrict__ Whl,
                          const float* __restrict__ Wout, const float* __restrict__ bhl,
                          const float* __restrict__ bout, const float* __restrict__ Wmap) {
    const size_t nX  = (size_t)H4 * 128;
    const size_t nCT = (size_t)H * OUTD;
    const size_t nM  = (size_t)EMB * OUTD / 2;
    const size_t total = nX + nCT + nM + OUTD;
    size_t stride = (size_t)gridDim.x * blockDim.x;
    for (size_t i = (size_t)blockIdx.x * blockDim.x + threadIdx.x; i < total; i += stride) {
        if (i < nX) {
            size_t r = i / 128;
            int c = 2 * (int)(i % 128);
            float lo = (c < IN_DIM + EMB)     ? Wih0[r * 246 + c]     : 0.f;
            float hi = (c + 1 < IN_DIM + EMB) ? Wih0[r * 246 + c + 1] : 0.f;
            g_WXp[i] = pack2(lo, hi);
        } else if (i < nX + nCT) {
            size_t k = i - nX;
            int c = (int)(k / OUTD), r = (int)(k % OUTD);
            float s = 0.f;
            #pragma unroll 4
            for (int kk = 0; kk < H2; kk++)
                s = fmaf(__ldg(Wout + r * H2 + kk), __ldg(Whl + (size_t)kk * H + c), s);
            g_WCBT[k] = s;
        } else if (i < nX + nCT + nM) {
            size_t k = i - nX - nCT;
            int r = (int)(k / (OUTD / 2)), q = (int)(k % (OUTD / 2));
            g_WMp[k] = pack2(Wmap[r * OUTD + 2 * q], Wmap[r * OUTD + 2 * q + 1]);
        } else {
            int r = (int)(i - nX - nCT - nM);
            float s = 0.f;
            #pragma unroll 4
            for (int kk = 0; kk < H2; kk++) s = fmaf(Wout[r * H2 + kk], bhl[kk], s);
            float bc = s + bout[r];
            g_bcomb[r] = bc;
            g_L[0][r] = bc; g_L[1][r] = bc;
        }
    }
}

// ---------------- core math -----------------------------------------------------------
__device__ __forceinline__ float wred(float a) {
    a += __shfl_xor_sync(0xffffffffu, a, 16);
    a += __shfl_xor_sync(0xffffffffu, a, 8);
    a += __shfl_xor_sync(0xffffffffu, a, 4);
    a += __shfl_xor_sync(0xffffffffu, a, 2);
    a += __shfl_xor_sync(0xffffffffu, a, 1);
    return a;
}
__device__ __forceinline__ int wredi(int a) {
    a += __shfl_xor_sync(0xffffffffu, a, 16);
    a += __shfl_xor_sync(0xffffffffu, a, 8);
    a += __shfl_xor_sync(0xffffffffu, a, 4);
    a += __shfl_xor_sync(0xffffffffu, a, 2);
    a += __shfl_xor_sync(0xffffffffu, a, 1);
    return a;
}
__device__ __forceinline__ float sigmoidf_(float x) { return 1.f / (1.f + expf(-x)); }

__device__ __forceinline__ void bffma2p(unsigned long long& acc, unsigned w,
                                        unsigned long long xp) {
    asm("{\n\t"
        ".reg .b32 lo;\n\t"
        ".reg .b64 wp;\n\t"
        "shl.b32 lo, %1, 16;\n\t"
        "mov.b64 wp, {lo, %1};\n\t"
        "fma.rn.f32x2 %0, wp, %2, %0;\n\t"
        "}" : "+l"(acc) : "r"(w), "l"(xp));
}
__device__ __forceinline__ float upsum(unsigned long long a) {
    return __uint_as_float((unsigned)a) + __uint_as_float((unsigned)(a >> 32));
}
__device__ __forceinline__ void bffma2(float& a0, float& a1, unsigned w, float x0, float x1) {
    asm("{\n\t"
        ".reg .b32 lo;\n\t"
        ".reg .b64 wp, xp, ap;\n\t"
        "shl.b32 lo, %2, 16;\n\t"
        "mov.b64 wp, {lo, %2};\n\t"
        "mov.b64 xp, {%3, %4};\n\t"
        "mov.b64 ap, {%0, %1};\n\t"
        "fma.rn.f32x2 ap, wp, xp, ap;\n\t"
        "mov.b64 {%0, %1}, ap;\n\t"
        "}" : "+f"(a0), "+f"(a1) : "r"(w), "f"(x0), "f"(x1));
}

// int8 3-row dot over 1536 cols (96 uint4 per row); x quantized in SMEM
__device__ __forceinline__ void dot3q(const uint4* __restrict__ q0,
                                      const uint4* __restrict__ q1,
                                      const uint4* __restrict__ q2,
                                      const uint4* __restrict__ xq, int lane,
                                      int& r0, int& r1, int& r2) {
    int a0 = 0, a1 = 0, a2 = 0;
    #pragma unroll
    for (int it = 0; it < 3; ++it) {
        uint4 x  = xq[it * 32 + lane];
        uint4 v0 = __ldcg(q0 + it * 32 + lane);
        uint4 v1 = __ldcg(q1 + it * 32 + lane);
        uint4 v2 = __ldcg(q2 + it * 32 + lane);
        a0 = __dp4a((int)v0.x, (int)x.x, a0); a0 = __dp4a((int)v0.y, (int)x.y, a0);
        a0 = __dp4a((int)v0.z, (int)x.z, a0); a0 = __dp4a((int)v0.w, (int)x.w, a0);
        a1 = __dp4a((int)v1.x, (int)x.x, a1); a1 = __dp4a((int)v1.y, (int)x.y, a1);
        a1 = __dp4a((int)v1.z, (int)x.z, a1); a1 = __dp4a((int)v1.w, (int)x.w, a1);
        a2 = __dp4a((int)v2.x, (int)x.x, a2); a2 = __dp4a((int)v2.y, (int)x.y, a2);
        a2 = __dp4a((int)v2.z, (int)x.z, a2); a2 = __dp4a((int)v2.w, (int)x.w, a2);
    }
    r0 = wredi(a0); r1 = wredi(a1); r2 = wredi(a2);
}

// quantize gathered float4 into one packed word
__device__ __forceinline__ unsigned quant4(float4 g, float inv) {
    int q0 = __float2int_rn(g.x * inv), q1 = __float2int_rn(g.y * inv);
    int q2 = __float2int_rn(g.z * inv), q3 = __float2int_rn(g.w * inv);
    return (q0 & 255) | ((q1 & 255) << 8) | ((q2 & 255) << 16) | ((q3 & 255) << 24);
}

#define BARC() asm volatile("bar.sync 1, 512;" ::: "memory")
#define BARP() asm volatile("bar.sync 2, 512;" ::: "memory")

__device__ __forceinline__ void bar_arrive_leader() {
    asm volatile("red.release.gpu.global.add.u32 [%0], 1;" :: "l"(&g_count) : "memory");
}
__device__ __forceinline__ void bar_poll_leader(unsigned target) {
    unsigned v;
    do {
        asm volatile("ld.acquire.gpu.global.u32 %0, [%1];" : "=r"(v) : "l"(&g_count) : "memory");
    } while (v < target);
}

// ---------------- persistent main kernel ----------------------------------------------
__global__ void __launch_bounds__(NTHR, 1) lstm_main(
    const float* __restrict__ inputVecs,
    const float* __restrict__ h0in, const float* __restrict__ c0in,
    const float* __restrict__ bi0, const float* __restrict__ bh0,
    const float* __restrict__ bi1, const float* __restrict__ bh1,
    const float* __restrict__ bm,
    float* __restrict__ out) {
    __shared__ __align__(16) float sxx[256];
    __shared__ __align__(16) unsigned sxq[QW];     // C quantized h0n
    __shared__ __align__(16) unsigned spq[QW];     // P quant buffer (h0n then h1n)
    __shared__ float sgmaxC[12], sgmaxP[12];
    __shared__ float sh1[12];
    __shared__ float sgate[48], sg1[48];
    __shared__ float pArow[48], pBrow[48];
    __shared__ float bA[48], bB[48];
    __shared__ float sy[OUTD], semb[EMB], sbm[EMB];

    const int tid = threadIdx.x, lane = tid & 31, bid = blockIdx.x;
    const bool isC = tid < 512;
    const int wid = tid >> 5;          // C: 0..15
    const int i0 = (wid & 15) * 3;

    // per-warp row ids and pointers
    int grow[3];
    #pragma unroll
    for (int i = 0; i < 3; i++) {
        int idx = i0 + i;
        grow[i] = (idx / 12) * H + bid * 12 + (idx % 12);
    }

    float cA = 0.f, cB = 0.f;
    if (isC && wid == 0 && lane < 12) {
        int j = bid * 12 + lane;
        cA = c0in[j]; cB = c0in[H + j];
    }
    if (tid < 48) {
        int g = (tid / 12) * H + bid * 12 + (tid % 12);
        bA[tid] = bi0[g] + bh0[g];
        bB[tid] = bi1[g] + bh1[g];
    }
    if (isC) for (int i = tid; i < EMB; i += 512) { semb[i] = 0.f; sbm[i] = __ldg(bm + i); }

    // C-side scales + pointers (ih1)
    float scI[3];
    const uint4 *qI[3], *wx[3];
    if (isC) {
        #pragma unroll
        for (int i = 0; i < 3; i++) {
            scI[i] = __ldg(&g_sI1[grow[i]]);
            qI[i] = reinterpret_cast<const uint4*>(g_QI1 + (size_t)grow[i] * QW);
            wx[i] = reinterpret_cast<const uint4*>(g_WXp + (size_t)grow[i] * 128);
        }
    }
    // P-side scales + pointers (hh0, hh1)
    float scH0[3], scH1[3];
    const uint4 *qH0[3], *qH1[3];
    if (!isC) {
        #pragma unroll
        for (int i = 0; i < 3; i++) {
            scH0[i] = __ldg(&g_sH0[grow[i]]);
            scH1[i] = __ldg(&g_sH1[grow[i]]);
            qH0[i] = reinterpret_cast<const uint4*>(g_QH0 + (size_t)grow[i] * QW);
            qH1[i] = reinterpret_cast<const uint4*>(g_QH1 + (size_t)grow[i] * QW);
        }
    }
    __syncthreads();

    // P prologue: initial hh partials from h0in (quantized path)
    if (!isC) {
        const int ptid = tid - 512;
        const int pw = wid & 15;
        #pragma unroll
        for (int half = 0; half < 2; half++) {
            float4 gv = make_float4(0.f, 0.f, 0.f, 0.f);
            if (ptid < 384) {
                gv = *reinterpret_cast<const float4*>(h0in + half * H + 4 * ptid);
                float m = fmaxf(fmaxf(fabsf(gv.x), fabsf(gv.y)), fmaxf(fabsf(gv.z), fabsf(gv.w)));
                #pragma unroll
                for (int o = 16; o; o >>= 1) m = fmaxf(m, __shfl_xor_sync(0xffffffffu, m, o));
                if (lane == 0 && pw < 12) sgmaxP[pw] = m;
            }
            BARP();
            float mx = 0.f;
            #pragma unroll
            for (int i = 0; i < 12; i++) mx = fmaxf(mx, sgmaxP[i]);
            float inv = (mx > 0.f) ? 127.f / mx : 0.f;
            float sxs = mx / 127.f;
            if (ptid < 384) spq[ptid] = quant4(gv, inv);
            BARP();
            int r0, r1, r2;
            if (half == 0) {
                dot3q(qH0[0], qH0[1], qH0[2], reinterpret_cast<const uint4*>(spq), lane, r0, r1, r2);
                if (lane == 0) {
                    pArow[i0] = (float)r0 * (scH0[0] * sxs);
                    pArow[i0 + 1] = (float)r1 * (scH0[1] * sxs);
                    pArow[i0 + 2] = (float)r2 * (scH0[2] * sxs);
                }
            } else {
                dot3q(qH1[0], qH1[1], qH1[2], reinterpret_cast<const uint4*>(spq), lane, r0, r1, r2);
                if (lane == 0) {
                    pBrow[i0] = (float)r0 * (scH1[0] * sxs);
                    pBrow[i0 + 1] = (float)r1 * (scH1[1] * sxs);
                    pBrow[i0 + 2] = (float)r2 * (scH1[2] * sxs);
                }
            }
            BARP();
        }
    }
    __syncthreads();

    unsigned ep1 = NBLK, ep2 = 2 * NBLK;

    for (int t = 0; t < T_STEPS; ++t) {
        const int par = t & 1;
        __syncthreads();   // step top: pArow/pBrow/semb handoff visible

        if (isC) {
            // ---- phase A (block-local): bf16 x/emb dot + pArow -> h0n ---------------
            if (tid < 256) {
                float v = 0.f;
                if (tid < IN_DIM)            v = __ldg(inputVecs + (size_t)t * IN_DIM + tid);
                else if (tid < IN_DIM + EMB) v = semb[tid - IN_DIM];
                sxx[tid] = v;
            }
            BARC();
            {
                unsigned long long A0 = 0ull, A1 = 0ull, A2 = 0ull;
                ulonglong2 xa = *reinterpret_cast<const ulonglong2*>(sxx + lane * 8);
                ulonglong2 xb = *reinterpret_cast<const ulonglong2*>(sxx + lane * 8 + 4);
                uint4 v0 = __ldcg(wx[0] + lane);
                uint4 v1 = __ldcg(wx[1] + lane);
                uint4 v2 = __ldcg(wx[2] + lane);
                bffma2p(A0, v0.x, xa.x); bffma2p(A0, v0.y, xa.y);
                bffma2p(A0, v0.z, xb.x); bffma2p(A0, v0.w, xb.y);
                bffma2p(A1, v1.x, xa.x); bffma2p(A1, v1.y, xa.y);
                bffma2p(A1, v1.z, xb.x); bffma2p(A1, v1.w, xb.y);
                bffma2p(A2, v2.x, xa.x); bffma2p(A2, v2.y, xa.y);
                bffma2p(A2, v2.z, xb.x); bffma2p(A2, v2.w, xb.y);
                float s0 = wred(upsum(A0)), s1 = wred(upsum(A1)), s2 = wred(upsum(A2));
                if (lane == 0) {
                    sgate[i0]     = s0 + pArow[i0]     + bA[i0];
                    sgate[i0 + 1] = s1 + pArow[i0 + 1] + bA[i0 + 1];
                    sgate[i0 + 2] = s2 + pArow[i0 + 2] + bA[i0 + 2];
                }
            }
            BARC();
            if (wid == 0 && lane < 12) {
                float gi = sigmoidf_(sgate[lane]);
                float gf = sigmoidf_(sgate[12 + lane]);
                float gg = tanhf    (sgate[24 + lane]);
                float go = sigmoidf_(sgate[36 + lane]);
                cA = gf * cA + gi * gg;
                g_h0v[bid * 12 + lane] = go * tanhf(cA);
            }
            BARC();
            if (tid == 0) { bar_arrive_leader(); bar_poll_leader(ep1); }   // bar1
            BARC();
            // ---- slot B: gather+quant h0n, int8 ih1 dot + pBrow -> h1n, logit -------
            float4 gv = make_float4(0.f, 0.f, 0.f, 0.f);
            if (tid < 384) {
                gv = __ldcg(reinterpret_cast<const float4*>(g_h0v) + tid);
                float m = fmaxf(fmaxf(fabsf(gv.x), fabsf(gv.y)), fmaxf(fabsf(gv.z), fabsf(gv.w)));
                #pragma unroll
                for (int o = 16; o; o >>= 1) m = fmaxf(m, __shfl_xor_sync(0xffffffffu, m, o));
                if (lane == 0 && wid < 12) sgmaxC[wid] = m;
            }
            BARC();
            float mx = 0.f;
            #pragma unroll
            for (int i = 0; i < 12; i++) mx = fmaxf(mx, sgmaxC[i]);
            float inv = (mx > 0.f) ? 127.f / mx : 0.f;
            float sxs = mx / 127.f;
            if (tid < 384) sxq[tid] = quant4(gv, inv);
            BARC();
            {
                int r0, r1, r2;
                dot3q(qI[0], qI[1], qI[2], reinterpret_cast<const uint4*>(sxq), lane, r0, r1, r2);
                if (lane == 0) {
                    sg1[i0]     = (float)r0 * (scI[0] * sxs) + pBrow[i0]     + bB[i0];
                    sg1[i0 + 1] = (float)r1 * (scI[1] * sxs) + pBrow[i0 + 1] + bB[i0 + 1];
                    sg1[i0 + 2] = (float)r2 * (scI[2] * sxs) + pBrow[i0 + 2] + bB[i0 + 2];
                }
            }
            BARC();
            if (wid == 0 && lane < 12) {
                float gi = sigmoidf_(sg1[lane]);
                float gf = sigmoidf_(sg1[12 + lane]);
                float gg = tanhf    (sg1[24 + lane]);
                float go = sigmoidf_(sg1[36 + lane]);
                cB = gf * cB + gi * gg;
                float h1n = go * tanhf(cB);
                g_h1v[bid * 12 + lane] = h1n;
                sh1[lane] = h1n;
            }
            BARC();
            if (tid < OUTD) {   // rank-12 logit contribution
                const float* wc = g_WCBT + (size_t)(bid * 12) * OUTD + tid;
                float p = 0.f;
                #pragma unroll
                for (int i = 0; i < 12; i++) p = fmaf(__ldg(wc + i * OUTD), sh1[i], p);
                asm volatile("red.relaxed.gpu.global.add.f32 [%0], %1;"
                             :: "l"(&g_L[par][tid]), "f"(p) : "memory");
            }
            BARC();
            if (tid == 0) { bar_arrive_leader(); bar_poll_leader(ep2); }   // bar2
            BARC();
            // ---- slot4 (block-local): softmax + emb ---------------------------------
            if (tid < OUTD) sy[tid] = __ldcg(&g_L[par][tid]);
            if (tid == 256) g_L[par ^ 1][bid] = __ldg(&g_bcomb[bid]);   // reset for t+2
            BARC();
            if (wid == 0) {
                float v0 = sy[lane], v1 = sy[lane + 32], v2 = sy[lane + 64], v3 = sy[lane + 96];
                float m = fmaxf(fmaxf(v0, v1), fmaxf(v2, v3));
                #pragma unroll
                for (int o = 16; o; o >>= 1) m = fmaxf(m, __shfl_xor_sync(0xffffffffu, m, o));
                float e0 = expf(v0 - m), e1 = expf(v1 - m), e2 = expf(v2 - m), e3 = expf(v3 - m);
                float s = wred(e0 + e1 + e2 + e3);
                float is = 1.f / s;
                e0 *= is; e1 *= is; e2 *= is; e3 *= is;
                sy[lane] = e0; sy[lane + 32] = e1; sy[lane + 64] = e2; sy[lane + 96] = e3;
                if (bid == 0) {
                    float* op = out + (size_t)t * OUTD;
                    op[lane] = e0; op[lane + 32] = e1; op[lane + 64] = e2; op[lane + 96] = e3;
                }
            }
            BARC();
            {   // emb = Wmap @ y + bm (bf16 pairs, L1-resident)
                float xa = sy[lane * 4], xb = sy[lane * 4 + 1];
                float xc = sy[lane * 4 + 2], xd = sy[lane * 4 + 3];
                #pragma unroll
                for (int q = 0; q < 8; q++) {
                    int r = wid * 8 + q;
                    const unsigned* wm = g_WMp + r * (OUTD / 2) + lane * 2;
                    float a0 = 0.f, a1 = 0.f;
                    bffma2(a0, a1, __ldg(wm), xa, xb);
                    bffma2(a0, a1, __ldg(wm + 1), xc, xd);
                    float s = wred(a0 + a1);
                    if (lane == 0) semb[r] = s + sbm[r];
                }
            }
        } else {
            // ============== P-group: hh prefetch for step t+1 ========================
            const int ptid = tid - 512;
            const int pw = wid & 15;
            if (ptid == 0) bar_poll_leader(ep1);
            BARP();
            float4 gv = make_float4(0.f, 0.f, 0.f, 0.f);
            if (ptid < 384) {
                gv = __ldcg(reinterpret_cast<const float4*>(g_h0v) + ptid);
                float m = fmaxf(fmaxf(fabsf(gv.x), fabsf(gv.y)), fmaxf(fabsf(gv.z), fabsf(gv.w)));
                #pragma unroll
                for (int o = 16; o; o >>= 1) m = fmaxf(m, __shfl_xor_sync(0xffffffffu, m, o));
                if (lane == 0 && pw < 12) sgmaxP[pw] = m;
            }
            BARP();
            {
                float mx = 0.f;
                #pragma unroll
                for (int i = 0; i < 12; i++) mx = fmaxf(mx, sgmaxP[i]);
                float inv = (mx > 0.f) ? 127.f / mx : 0.f;
                float sxs = mx / 127.f;
                if (ptid < 384) spq[ptid] = quant4(gv, inv);
                BARP();
                int r0, r1, r2;
                dot3q(qH0[0], qH0[1], qH0[2], reinterpret_cast<const uint4*>(spq), lane, r0, r1, r2);
                if (lane == 0) {
                    pArow[i0]     = (float)r0 * (scH0[0] * sxs);
                    pArow[i0 + 1] = (float)r1 * (scH0[1] * sxs);
                    pArow[i0 + 2] = (float)r2 * (scH0[2] * sxs);
                }
            }
            if (ptid == 0) bar_poll_leader(ep2);
            BARP();
            gv = make_float4(0.f, 0.f, 0.f, 0.f);
            if (ptid < 384) {
                gv = __ldcg(reinterpret_cast<const float4*>(g_h1v) + ptid);
                float m = fmaxf(fmaxf(fabsf(gv.x), fabsf(gv.y)), fmaxf(fabsf(gv.z), fabsf(gv.w)));
                #pragma unroll
                for (int o = 16; o; o >>= 1) m = fmaxf(m, __shfl_xor_sync(0xffffffffu, m, o));
                if (lane == 0 && pw < 12) sgmaxP[pw] = m;
            }
            BARP();
            {
                float mx = 0.f;
                #pragma unroll
                for (int i = 0; i < 12; i++) mx = fmaxf(mx, sgmaxP[i]);
                float inv = (mx > 0.f) ? 127.f / mx : 0.f;
                float sxs = mx / 127.f;
                if (ptid < 384) spq[ptid] = quant4(gv, inv);
                BARP();
                int r0, r1, r2;
                dot3q(qH1[0], qH1[1], qH1[2], reinterpret_cast<const uint4*>(spq), lane, r0, r1, r2);
                if (lane == 0) {
                    pBrow[i0]     = (float)r0 * (scH1[0] * sxs);
                    pBrow[i0 + 1] = (float)r1 * (scH1[1] * sxs);
                    pBrow[i0 + 2] = (float)r2 * (scH1[2] * sxs);
                }
            }
        }
        ep1 += 2 * NBLK; ep2 += 2 * NBLK;
    }

    // end-of-launch reset (last arriver) for graph replay
    __syncthreads();
    if (tid == 0) {
        __threadfence();
        if (atomicAdd(&g_done, 1u) == NBLK - 1) {
            g_count = 0u;
            g_done = 0u;
            __threadfence();
        }
    }
}

// ---------------- launch --------------------------------------------------------------
extern "C" void kernel_launch(void* const* d_in, const int* in_sizes, int n_in,
                              void* d_out, int out_size) {
    const float* inputVecs = (const float*)d_in[0];
    const float* h0    = (const float*)d_in[1];
    const float* c0    = (const float*)d_in[2];
    const float* W_ih0 = (const float*)d_in[3];
    const float* W_hh0 = (const float*)d_in[4];
    const float* b_ih0 = (const float*)d_in[5];
    const float* b_hh0 = (const float*)d_in[6];
    const float* W_ih1 = (const float*)d_in[7];
    const float* W_hh1 = (const float*)d_in[8];
    const float* b_ih1 = (const float*)d_in[9];
    const float* b_hh1 = (const float*)d_in[10];
    const float* W_hl  = (const float*)d_in[11];
    const float* b_hl  = (const float*)d_in[12];
    const float* W_out = (const float*)d_in[13];
    const float* b_out = (const float*)d_in[14];
    const float* W_map = (const float*)d_in[15];
    const float* b_map = (const float*)d_in[16];

    pack_quant<<<(3 * H4 + 7) / 8, 256>>>(W_ih1, W_hh0, W_hh1);
    pack_rest<<<1024, 256>>>(W_ih0, W_hl, W_out, b_hl, b_out, W_map);
    lstm_main<<<NBLK, NTHR>>>(inputVecs, h0, c0,
                              b_ih0, b_hh0, b_ih1, b_hh1,
                              b_map, (float*)d_out);
}

// round 13
// speedup vs baseline: 2.8227x; 1.1347x over previous
#include <cuda_runtime.h>
#include <cuda_bf16.h>

#define T_STEPS 2048
#define IN_DIM  118
#define EMB     128
#define H       1536
#define H4      6144
#define H2      1024
#define OUTD    128
#define QW      384    // int8 words per 1536-col row
#define NBLK    128
#define NTHR    1024   // 16 critical (C) warps + 16 prefetch (P) warps

// ---------------- device-global scratch ----------------------------------------------
__device__ __align__(128) unsigned g_QI1[(size_t)H4 * QW];  // W_ih1 int8 rows (9.4MB)
__device__ __align__(128) unsigned g_QH0[(size_t)H4 * QW];  // W_hh0
__device__ __align__(128) unsigned g_QH1[(size_t)H4 * QW];  // W_hh1
__device__ float g_sI1[H4], g_sH0[H4], g_sH1[H4];           // per-row scales
__device__ __align__(128) unsigned g_WXp[(size_t)H4 * 128]; // W_ih0 x/emb bf16 pairs (3MB)
__device__ __align__(128) float g_WCBT[(size_t)H * OUTD];   // (W_out@W_hl)^T  [c][r]
__device__ __align__(128) unsigned g_WMp[EMB * OUTD / 2];   // W_map bf16 pairs
__device__ float g_bcomb[OUTD];
__device__ __align__(16) unsigned g_h0q[NBLK * 3];          // packed int8 h0 (scale 1/127)
__device__ __align__(16) unsigned g_h1q[NBLK * 3];          // packed int8 h1
__device__ float g_L[2][OUTD];
__device__ unsigned g_count = 0;
__device__ unsigned g_done  = 0;

// ---------------- packing -------------------------------------------------------------
__device__ __forceinline__ unsigned pack2(float wlo, float whi) {
    unsigned lo16 = (unsigned)__bfloat16_as_ushort(__float2bfloat16(wlo));
    unsigned base = __float_as_uint(whi) & 0xffff0000u;
    unsigned c0 = base | lo16, c1 = (base + 0x10000u) | lo16, c2 = (base - 0x10000u) | lo16;
    float d0 = fabsf(__uint_as_float(c0) - whi);
    float d1 = fabsf(__uint_as_float(c1) - whi);
    float d2 = fabsf(__uint_as_float(c2) - whi);
    unsigned best = c0; float bd = d0;
    if (d1 < bd) { bd = d1; best = c1; }
    if (d2 < bd) { best = c2; }
    return best;
}

__global__ void pack_quant(const float* __restrict__ Wih1, const float* __restrict__ Whh0,
                           const float* __restrict__ Whh1) {
    int gw = blockIdx.x * (blockDim.x >> 5) + (threadIdx.x >> 5);
    int lane = threadIdx.x & 31;
    if (gw >= 3 * H4) return;
    int m = gw / H4, r = gw % H4;
    const float* M = (m == 0) ? Wih1 : (m == 1) ? Whh0 : Whh1;
    unsigned* D = (m == 0) ? g_QI1 : (m == 1) ? g_QH0 : g_QH1;
    float* S = (m == 0) ? g_sI1 : (m == 1) ? g_sH0 : g_sH1;
    const float* row = M + (size_t)r * H;
    float v[48];
    float mx = 0.f;
    #pragma unroll
    for (int i = 0; i < 48; i++) { v[i] = row[lane * 48 + i]; mx = fmaxf(mx, fabsf(v[i])); }
    #pragma unroll
    for (int o = 16; o; o >>= 1) mx = fmaxf(mx, __shfl_xor_sync(0xffffffffu, mx, o));
    float inv = (mx > 0.f) ? 127.f / mx : 0.f;
    unsigned* drow = D + (size_t)r * QW + lane * 12;
    #pragma unroll
    for (int w = 0; w < 12; w++) {
        int q0 = __float2int_rn(v[4 * w] * inv);
        int q1 = __float2int_rn(v[4 * w + 1] * inv);
        int q2 = __float2int_rn(v[4 * w + 2] * inv);
        int q3 = __float2int_rn(v[4 * w + 3] * inv);
        drow[w] = (q0 & 255) | ((q1 & 255) << 8) | ((q2 & 255) << 16) | ((q3 & 255) << 24);
    }
    if (lane == 0) S[r] = mx / 127.f;
}

__global__ void pack_rest(const float* __restrict__ Wih0, const float* __restrict__ Whl,
                          const float* __restrict__ Wout, const float* __restrict__ bhl,
                          const float* __restrict__ bout, const float* __restrict__ Wmap) {
    const size_t nX  = (size_t)H4 * 128;
    const size_t nCT = (size_t)H * OUTD;
    const size_t nM  = (size_t)EMB * OUTD / 2;
    const size_t total = nX + nCT + nM + OUTD;
    size_t stride = (size_t)gridDim.x * blockDim.x;
    for (size_t i = (size_t)blockIdx.x * blockDim.x + threadIdx.x; i < total; i += stride) {
        if (i < nX) {
            size_t r = i / 128;
            int c = 2 * (int)(i % 128);
            float lo = (c < IN_DIM + EMB)     ? Wih0[r * 246 + c]     : 0.f;
            float hi = (c + 1 < IN_DIM + EMB) ? Wih0[r * 246 + c + 1] : 0.f;
            g_WXp[i] = pack2(lo, hi);
        } else if (i < nX + nCT) {
            size_t k = i - nX;
            int c = (int)(k / OUTD), r = (int)(k % OUTD);
            float s = 0.f;
            #pragma unroll 4
            for (int kk = 0; kk < H2; kk++)
                s = fmaf(__ldg(Wout + r * H2 + kk), __ldg(Whl + (size_t)kk * H + c), s);
            g_WCBT[k] = s;
        } else if (i < nX + nCT + nM) {
            size_t k = i - nX - nCT;
            int r = (int)(k / (OUTD / 2)), q = (int)(k % (OUTD / 2));
            g_WMp[k] = pack2(Wmap[r * OUTD + 2 * q], Wmap[r * OUTD + 2 * q + 1]);
        } else {
            int r = (int)(i - nX - nCT - nM);
            float s = 0.f;
            #pragma unroll 4
            for (int kk = 0; kk < H2; kk++) s = fmaf(Wout[r * H2 + kk], bhl[kk], s);
            float bc = s + bout[r];
            g_bcomb[r] = bc;
            g_L[0][r] = bc; g_L[1][r] = bc;
        }
    }
}

// ---------------- core math -----------------------------------------------------------
__device__ __forceinline__ float wred(float a) {
    a += __shfl_xor_sync(0xffffffffu, a, 16);
    a += __shfl_xor_sync(0xffffffffu, a, 8);
    a += __shfl_xor_sync(0xffffffffu, a, 4);
    a += __shfl_xor_sync(0xffffffffu, a, 2);
    a += __shfl_xor_sync(0xffffffffu, a, 1);
    return a;
}
__device__ __forceinline__ int wredi(int a) {
    a += __shfl_xor_sync(0xffffffffu, a, 16);
    a += __shfl_xor_sync(0xffffffffu, a, 8);
    a += __shfl_xor_sync(0xffffffffu, a, 4);
    a += __shfl_xor_sync(0xffffffffu, a, 2);
    a += __shfl_xor_sync(0xffffffffu, a, 1);
    return a;
}
__device__ __forceinline__ float sigf(float x) {
    return __fdividef(1.f, 1.f + __expf(-x));
}
__device__ __forceinline__ float tanhf_fast(float x) {
    return __fdividef(2.f, 1.f + __expf(-2.f * x)) - 1.f;
}

__device__ __forceinline__ void bffma2p(unsigned long long& acc, unsigned w,
                                        unsigned long long xp) {
    asm("{\n\t"
        ".reg .b32 lo;\n\t"
        ".reg .b64 wp;\n\t"
        "shl.b32 lo, %1, 16;\n\t"
        "mov.b64 wp, {lo, %1};\n\t"
        "fma.rn.f32x2 %0, wp, %2, %0;\n\t"
        "}" : "+l"(acc) : "r"(w), "l"(xp));
}
__device__ __forceinline__ float upsum(unsigned long long a) {
    return __uint_as_float((unsigned)a) + __uint_as_float((unsigned)(a >> 32));
}
__device__ __forceinline__ void bffma2(float& a0, float& a1, unsigned w, float x0, float x1) {
    asm("{\n\t"
        ".reg .b32 lo;\n\t"
        ".reg .b64 wp, xp, ap;\n\t"
        "shl.b32 lo, %2, 16;\n\t"
        "mov.b64 wp, {lo, %2};\n\t"
        "mov.b64 xp, {%3, %4};\n\t"
        "mov.b64 ap, {%0, %1};\n\t"
        "fma.rn.f32x2 ap, wp, xp, ap;\n\t"
        "mov.b64 {%0, %1}, ap;\n\t"
        "}" : "+f"(a0), "+f"(a1) : "r"(w), "f"(x0), "f"(x1));
}

// int8 3-row dot over 1536 cols; weights from L2 (.cg) — P-group streams
__device__ __forceinline__ void dot3q_cg(const uint4* __restrict__ q0,
                                         const uint4* __restrict__ q1,
                                         const uint4* __restrict__ q2,
                                         const uint4* __restrict__ xq, int lane,
                                         int& r0, int& r1, int& r2) {
    int a0 = 0, a1 = 0, a2 = 0;
    #pragma unroll
    for (int it = 0; it < 3; ++it) {
        uint4 x  = xq[it * 32 + lane];
        uint4 v0 = __ldcg(q0 + it * 32 + lane);
        uint4 v1 = __ldcg(q1 + it * 32 + lane);
        uint4 v2 = __ldcg(q2 + it * 32 + lane);
        a0 = __dp4a((int)v0.x, (int)x.x, a0); a0 = __dp4a((int)v0.y, (int)x.y, a0);
        a0 = __dp4a((int)v0.z, (int)x.z, a0); a0 = __dp4a((int)v0.w, (int)x.w, a0);
        a1 = __dp4a((int)v1.x, (int)x.x, a1); a1 = __dp4a((int)v1.y, (int)x.y, a1);
        a1 = __dp4a((int)v1.z, (int)x.z, a1); a1 = __dp4a((int)v1.w, (int)x.w, a1);
        a2 = __dp4a((int)v2.x, (int)x.x, a2); a2 = __dp4a((int)v2.y, (int)x.y, a2);
        a2 = __dp4a((int)v2.z, (int)x.z, a2); a2 = __dp4a((int)v2.w, (int)x.w, a2);
    }
    r0 = wredi(a0); r1 = wredi(a1); r2 = wredi(a2);
}

// same but L1-cached (.ca) — C-group critical ih1 slice, L1-resident across steps
__device__ __forceinline__ void dot3q_l1(const uint4* __restrict__ q0,
                                         const uint4* __restrict__ q1,
                                         const uint4* __restrict__ q2,
                                         const uint4* __restrict__ xq, int lane,
                                         int& r0, int& r1, int& r2) {
    int a0 = 0, a1 = 0, a2 = 0;
    #pragma unroll
    for (int it = 0; it < 3; ++it) {
        uint4 x  = xq[it * 32 + lane];
        uint4 v0 = __ldg(q0 + it * 32 + lane);
        uint4 v1 = __ldg(q1 + it * 32 + lane);
        uint4 v2 = __ldg(q2 + it * 32 + lane);
        a0 = __dp4a((int)v0.x, (int)x.x, a0); a0 = __dp4a((int)v0.y, (int)x.y, a0);
        a0 = __dp4a((int)v0.z, (int)x.z, a0); a0 = __dp4a((int)v0.w, (int)x.w, a0);
        a1 = __dp4a((int)v1.x, (int)x.x, a1); a1 = __dp4a((int)v1.y, (int)x.y, a1);
        a1 = __dp4a((int)v1.z, (int)x.z, a1); a1 = __dp4a((int)v1.w, (int)x.w, a1);
        a2 = __dp4a((int)v2.x, (int)x.x, a2); a2 = __dp4a((int)v2.y, (int)x.y, a2);
        a2 = __dp4a((int)v2.z, (int)x.z, a2); a2 = __dp4a((int)v2.w, (int)x.w, a2);
    }
    r0 = wredi(a0); r1 = wredi(a1); r2 = wredi(a2);
}

__device__ __forceinline__ unsigned quant4(float4 g, float inv) {
    int q0 = __float2int_rn(g.x * inv), q1 = __float2int_rn(g.y * inv);
    int q2 = __float2int_rn(g.z * inv), q3 = __float2int_rn(g.w * inv);
    return (q0 & 255) | ((q1 & 255) << 8) | ((q2 & 255) << 16) | ((q3 & 255) << 24);
}

#define BARC() asm volatile("bar.sync 1, 512;" ::: "memory")
#define BARP() asm volatile("bar.sync 2, 512;" ::: "memory")

__device__ __forceinline__ void bar_arrive_leader() {
    asm volatile("red.release.gpu.global.add.u32 [%0], 1;" :: "l"(&g_count) : "memory");
}
__device__ __forceinline__ void bar_poll_leader(unsigned target) {
    unsigned v;
    do {
        asm volatile("ld.acquire.gpu.global.u32 %0, [%1];" : "=r"(v) : "l"(&g_count) : "memory");
    } while (v < target);
}

// ---------------- persistent main kernel ----------------------------------------------
__global__ void __launch_bounds__(NTHR, 1) lstm_main(
    const float* __restrict__ inputVecs,
    const float* __restrict__ h0in, const float* __restrict__ c0in,
    const float* __restrict__ bi0, const float* __restrict__ bh0,
    const float* __restrict__ bi1, const float* __restrict__ bh1,
    const float* __restrict__ bm,
    float* __restrict__ out) {
    __shared__ __align__(16) float sxx[256];
    __shared__ __align__(16) unsigned sxq[QW];     // C quantized h0n (fixed scale 1/127)
    __shared__ __align__(16) unsigned spq[QW];     // P quant buffer
    __shared__ float sgmaxP[12];
    __shared__ float sh1[12];
    __shared__ float sgate[48], sg1[48];
    __shared__ float pArow[48], pBrow[48];
    __shared__ float bA[48], bB[48];
    __shared__ float sy[OUTD], semb[EMB], sbm[EMB];

    const int tid = threadIdx.x, lane = tid & 31, bid = blockIdx.x;
    const bool isC = tid < 512;
    const int wid = tid >> 5;          // C: 0..15
    const int i0 = (wid & 15) * 3;
    const float QS = 1.f / 127.f;      // fixed h scale

    int grow[3];
    #pragma unroll
    for (int i = 0; i < 3; i++) {
        int idx = i0 + i;
        grow[i] = (idx / 12) * H + bid * 12 + (idx % 12);
    }

    float cA = 0.f, cB = 0.f;
    if (isC && wid == 0 && lane < 12) {
        int j = bid * 12 + lane;
        cA = c0in[j]; cB = c0in[H + j];
    }
    if (tid < 48) {
        int g = (tid / 12) * H + bid * 12 + (tid % 12);
        bA[tid] = bi0[g] + bh0[g];
        bB[tid] = bi1[g] + bh1[g];
    }
    if (isC) for (int i = tid; i < EMB; i += 512) { semb[i] = 0.f; sbm[i] = __ldg(bm + i); }

    float scI[3];
    const uint4 *qI[3], *wx[3];
    if (isC) {
        #pragma unroll
        for (int i = 0; i < 3; i++) {
            scI[i] = __ldg(&g_sI1[grow[i]]) * QS;
            qI[i] = reinterpret_cast<const uint4*>(g_QI1 + (size_t)grow[i] * QW);
            wx[i] = reinterpret_cast<const uint4*>(g_WXp + (size_t)grow[i] * 128);
        }
    }
    float scH0[3], scH1[3];
    const uint4 *qH0[3], *qH1[3];
    if (!isC) {
        #pragma unroll
        for (int i = 0; i < 3; i++) {
            scH0[i] = __ldg(&g_sH0[grow[i]]);
            scH1[i] = __ldg(&g_sH1[grow[i]]);
            qH0[i] = reinterpret_cast<const uint4*>(g_QH0 + (size_t)grow[i] * QW);
            qH1[i] = reinterpret_cast<const uint4*>(g_QH1 + (size_t)grow[i] * QW);
        }
    }
    __syncthreads();

    // P prologue: initial hh partials from h0in (dynamic scale — h0in unbounded)
    if (!isC) {
        const int ptid = tid - 512;
        const int pw = wid & 15;
        #pragma unroll
        for (int half = 0; half < 2; half++) {
            float4 gv = make_float4(0.f, 0.f, 0.f, 0.f);
            if (ptid < 384) {
                gv = *reinterpret_cast<const float4*>(h0in + half * H + 4 * ptid);
                float m = fmaxf(fmaxf(fabsf(gv.x), fabsf(gv.y)), fmaxf(fabsf(gv.z), fabsf(gv.w)));
                #pragma unroll
                for (int o = 16; o; o >>= 1) m = fmaxf(m, __shfl_xor_sync(0xffffffffu, m, o));
                if (lane == 0 && pw < 12) sgmaxP[pw] = m;
            }
            BARP();
            float mx = 0.f;
            #pragma unroll
            for (int i = 0; i < 12; i++) mx = fmaxf(mx, sgmaxP[i]);
            float inv = (mx > 0.f) ? 127.f / mx : 0.f;
            float sxs = mx / 127.f;
            if (ptid < 384) spq[ptid] = quant4(gv, inv);
            BARP();
            int r0, r1, r2;
            if (half == 0) {
                dot3q_cg(qH0[0], qH0[1], qH0[2], reinterpret_cast<const uint4*>(spq), lane, r0, r1, r2);
                if (lane == 0) {
                    pArow[i0]     = (float)r0 * (scH0[0] * sxs);
                    pArow[i0 + 1] = (float)r1 * (scH0[1] * sxs);
                    pArow[i0 + 2] = (float)r2 * (scH0[2] * sxs);
                }
            } else {
                dot3q_cg(qH1[0], qH1[1], qH1[2], reinterpret_cast<const uint4*>(spq), lane, r0, r1, r2);
                if (lane == 0) {
                    pBrow[i0]     = (float)r0 * (scH1[0] * sxs);
                    pBrow[i0 + 1] = (float)r1 * (scH1[1] * sxs);
                    pBrow[i0 + 2] = (float)r2 * (scH1[2] * sxs);
                }
            }
            BARP();
        }
    }
    __syncthreads();

    unsigned ep1 = NBLK, ep2 = 2 * NBLK;

    for (int t = 0; t < T_STEPS; ++t) {
        const int par = t & 1;
        __syncthreads();   // step top: pArow/pBrow/semb handoff visible

        if (isC) {
            // ---- phase A (block-local): bf16 x/emb dot + pArow -> h0n (quant store) -
            if (tid < 256) {
                float v = 0.f;
                if (tid < IN_DIM)            v = __ldg(inputVecs + (size_t)t * IN_DIM + tid);
                else if (tid < IN_DIM + EMB) v = semb[tid - IN_DIM];
                sxx[tid] = v;
            }
            BARC();
            {
                unsigned long long A0 = 0ull, A1 = 0ull, A2 = 0ull;
                ulonglong2 xa = *reinterpret_cast<const ulonglong2*>(sxx + lane * 8);
                ulonglong2 xb = *reinterpret_cast<const ulonglong2*>(sxx + lane * 8 + 4);
                uint4 v0 = __ldg(wx[0] + lane);
                uint4 v1 = __ldg(wx[1] + lane);
                uint4 v2 = __ldg(wx[2] + lane);
                bffma2p(A0, v0.x, xa.x); bffma2p(A0, v0.y, xa.y);
                bffma2p(A0, v0.z, xb.x); bffma2p(A0, v0.w, xb.y);
                bffma2p(A1, v1.x, xa.x); bffma2p(A1, v1.y, xa.y);
                bffma2p(A1, v1.z, xb.x); bffma2p(A1, v1.w, xb.y);
                bffma2p(A2, v2.x, xa.x); bffma2p(A2, v2.y, xa.y);
                bffma2p(A2, v2.z, xb.x); bffma2p(A2, v2.w, xb.y);
                float s0 = wred(upsum(A0)), s1 = wred(upsum(A1)), s2 = wred(upsum(A2));
                if (lane == 0) {
                    sgate[i0]     = s0 + pArow[i0]     + bA[i0];
                    sgate[i0 + 1] = s1 + pArow[i0 + 1] + bA[i0 + 1];
                    sgate[i0 + 2] = s2 + pArow[i0 + 2] + bA[i0 + 2];
                }
            }
            BARC();
            if (wid == 0) {
                unsigned bq = 0;
                if (lane < 12) {
                    float gi = sigf(sgate[lane]);
                    float gf = sigf(sgate[12 + lane]);
                    float gg = tanhf_fast(sgate[24 + lane]);
                    float go = sigf(sgate[36 + lane]);
                    cA = gf * cA + gi * gg;
                    float h = go * tanhf_fast(cA);
                    bq = (unsigned)__float2int_rn(h * 127.f) & 255u;
                }
                unsigned p0 = __shfl_sync(0xffffffffu, bq, (lane * 4) & 31);
                unsigned p1 = __shfl_sync(0xffffffffu, bq, (lane * 4 + 1) & 31);
                unsigned p2 = __shfl_sync(0xffffffffu, bq, (lane * 4 + 2) & 31);
                unsigned p3 = __shfl_sync(0xffffffffu, bq, (lane * 4 + 3) & 31);
                if (lane < 3)
                    g_h0q[bid * 3 + lane] = p0 | (p1 << 8) | (p2 << 16) | (p3 << 24);
                __syncwarp();
                if (lane == 0) { bar_arrive_leader(); bar_poll_leader(ep1); }   // bar1
            }
            BARC();     // all C released once warp0 passed bar1
            // ---- slot B: gather h0q, int8 ih1 dot + pBrow -> h1n, logit -------------
            if (tid < 96)
                reinterpret_cast<uint4*>(sxq)[tid] =
                    __ldcg(reinterpret_cast<const uint4*>(g_h0q) + tid);
            BARC();
            {
                int r0, r1, r2;
                dot3q_l1(qI[0], qI[1], qI[2], reinterpret_cast<const uint4*>(sxq), lane, r0, r1, r2);
                if (lane == 0) {
                    sg1[i0]     = (float)r0 * scI[0] + pBrow[i0]     + bB[i0];
                    sg1[i0 + 1] = (float)r1 * scI[1] + pBrow[i0 + 1] + bB[i0 + 1];
                    sg1[i0 + 2] = (float)r2 * scI[2] + pBrow[i0 + 2] + bB[i0 + 2];
                }
            }
            BARC();
            if (wid == 0) {
                unsigned bq = 0;
                if (lane < 12) {
                    float gi = sigf(sg1[lane]);
                    float gf = sigf(sg1[12 + lane]);
                    float gg = tanhf_fast(sg1[24 + lane]);
                    float go = sigf(sg1[36 + lane]);
                    cB = gf * cB + gi * gg;
                    float h1n = go * tanhf_fast(cB);
                    sh1[lane] = h1n;
                    bq = (unsigned)__float2int_rn(h1n * 127.f) & 255u;
                }
                unsigned p0 = __shfl_sync(0xffffffffu, bq, (lane * 4) & 31);
                unsigned p1 = __shfl_sync(0xffffffffu, bq, (lane * 4 + 1) & 31);
                unsigned p2 = __shfl_sync(0xffffffffu, bq, (lane * 4 + 2) & 31);
                unsigned p3 = __shfl_sync(0xffffffffu, bq, (lane * 4 + 3) & 31);
                if (lane < 3)
                    g_h1q[bid * 3 + lane] = p0 | (p1 << 8) | (p2 << 16) | (p3 << 24);
            }
            BARC();     // sh1 + h1q visible
            if (tid < OUTD) {   // rank-12 logit contribution
                const float* wc = g_WCBT + (size_t)(bid * 12) * OUTD + tid;
                float p = 0.f;
                #pragma unroll
                for (int i = 0; i < 12; i++) p = fmaf(__ldg(wc + i * OUTD), sh1[i], p);
                asm volatile("red.relaxed.gpu.global.add.f32 [%0], %1;"
                             :: "l"(&g_L[par][tid]), "f"(p) : "memory");
            }
            BARC();
            if (tid == 0) { bar_arrive_leader(); bar_poll_leader(ep2); }   // bar2
            BARC();
            // ---- slot4 (block-local): softmax + emb ---------------------------------
            if (tid == 256) g_L[par ^ 1][bid] = __ldg(&g_bcomb[bid]);   // reset for t+2
            if (wid == 0) {
                float v0 = __ldcg(&g_L[par][lane]);
                float v1 = __ldcg(&g_L[par][lane + 32]);
                float v2 = __ldcg(&g_L[par][lane + 64]);
                float v3 = __ldcg(&g_L[par][lane + 96]);
                float m = fmaxf(fmaxf(v0, v1), fmaxf(v2, v3));
                #pragma unroll
                for (int o = 16; o; o >>= 1) m = fmaxf(m, __shfl_xor_sync(0xffffffffu, m, o));
                float e0 = __expf(v0 - m), e1 = __expf(v1 - m);
                float e2 = __expf(v2 - m), e3 = __expf(v3 - m);
                float s = wred(e0 + e1 + e2 + e3);
                float is = __fdividef(1.f, s);
                e0 *= is; e1 *= is; e2 *= is; e3 *= is;
                sy[lane] = e0; sy[lane + 32] = e1; sy[lane + 64] = e2; sy[lane + 96] = e3;
                if (bid == 0) {
                    float* op = out + (size_t)t * OUTD;
                    op[lane] = e0; op[lane + 32] = e1; op[lane + 64] = e2; op[lane + 96] = e3;
                }
            }
            BARC();
            {   // emb = Wmap @ y + bm (bf16 pairs, L1-resident)
                float xa = sy[lane * 4], xb = sy[lane * 4 + 1];
                float xc = sy[lane * 4 + 2], xd = sy[lane * 4 + 3];
                #pragma unroll
                for (int q = 0; q < 8; q++) {
                    int r = wid * 8 + q;
                    const unsigned* wm = g_WMp + r * (OUTD / 2) + lane * 2;
                    float a0 = 0.f, a1 = 0.f;
                    bffma2(a0, a1, __ldg(wm), xa, xb);
                    bffma2(a0, a1, __ldg(wm + 1), xc, xd);
                    float s = wred(a0 + a1);
                    if (lane == 0) semb[r] = s + sbm[r];
                }
            }
        } else {
            // ============== P-group: hh prefetch for step t+1 ========================
            const int ptid = tid - 512;
            if (ptid == 0) bar_poll_leader(ep1);
            BARP();
            if (ptid < 96)
                reinterpret_cast<uint4*>(spq)[ptid] =
                    __ldcg(reinterpret_cast<const uint4*>(g_h0q) + ptid);
            BARP();
            {
                int r0, r1, r2;
                dot3q_cg(qH0[0], qH0[1], qH0[2], reinterpret_cast<const uint4*>(spq), lane, r0, r1, r2);
                if (lane == 0) {
                    pArow[i0]     = (float)r0 * (scH0[0] * QS);
                    pArow[i0 + 1] = (float)r1 * (scH0[1] * QS);
                    pArow[i0 + 2] = (float)r2 * (scH0[2] * QS);
                }
            }
            if (ptid == 0) bar_poll_leader(ep2);
            BARP();
            if (ptid < 96)
                reinterpret_cast<uint4*>(spq)[ptid] =
                    __ldcg(reinterpret_cast<const uint4*>(g_h1q) + ptid);
            BARP();
            {
                int r0, r1, r2;
                dot3q_cg(qH1[0], qH1[1], qH1[2], reinterpret_cast<const uint4*>(spq), lane, r0, r1, r2);
                if (lane == 0) {
                    pBrow[i0]     = (float)r0 * (scH1[0] * QS);
                    pBrow[i0 + 1] = (float)r1 * (scH1[1] * QS);
                    pBrow[i0 + 2] = (float)r2 * (scH1[2] * QS);
                }
            }
        }
        ep1 += 2 * NBLK; ep2 += 2 * NBLK;
    }

    // end-of-launch reset (last arriver) for graph replay
    __syncthreads();
    if (tid == 0) {
        __threadfence();
        if (atomicAdd(&g_done, 1u) == NBLK - 1) {
            g_count = 0u;
            g_done = 0u;
            __threadfence();
        }
    }
}

// ---------------- launch --------------------------------------------------------------
extern "C" void kernel_launch(void* const* d_in, const int* in_sizes, int n_in,
                              void* d_out, int out_size) {
    const float* inputVecs = (const float*)d_in[0];
    const float* h0    = (const float*)d_in[1];
    const float* c0    = (const float*)d_in[2];
    const float* W_ih0 = (const float*)d_in[3];
    const float* W_hh0 = (const float*)d_in[4];
    const float* b_ih0 = (const float*)d_in[5];
    const float* b_hh0 = (const float*)d_in[6];
    const float* W_ih1 = (const float*)d_in[7];
    const float* W_hh1 = (const float*)d_in[8];
    const float* b_ih1 = (const float*)d_in[9];
    const float* b_hh1 = (const float*)d_in[10];
    const float* W_hl  = (const float*)d_in[11];
    const float* b_hl  = (const float*)d_in[12];
    const float* W_out = (const float*)d_in[13];
    const float* b_out = (const float*)d_in[14];
    const float* W_map = (const float*)d_in[15];
    const float* b_map = (const float*)d_in[16];

    pack_quant<<<(3 * H4 + 7) / 8, 256>>>(W_ih1, W_hh0, W_hh1);
    pack_rest<<<1024, 256>>>(W_ih0, W_hl, W_out, b_hl, b_out, W_map);
    lstm_main<<<NBLK, NTHR>>>(inputVecs, h0, c0,
                              b_ih0, b_hh0, b_ih1, b_hh1,
                              b_map, (float*)d_out);
}

// round 14
// speedup vs baseline: 2.9789x; 1.0553x over previous
#include <cuda_runtime.h>
#include <cuda_bf16.h>

#define T_STEPS 2048
#define IN_DIM  118
#define EMB     128
#define H       1536
#define H4      6144
#define H2      1024
#define OUTD    128
#define QW      384    // int8 words per 1536-col row
#define NBLK    128
#define NTHR    1024   // 16 critical (C) warps + 16 prefetch (P) warps

// ---------------- device-global scratch ----------------------------------------------
__device__ __align__(128) unsigned g_QI1[(size_t)H4 * QW];  // W_ih1 int8 rows (9.4MB)
__device__ __align__(128) unsigned g_QH0[(size_t)H4 * QW];  // W_hh0
__device__ __align__(128) unsigned g_QH1[(size_t)H4 * QW];  // W_hh1
__device__ float g_sI1[H4], g_sH0[H4], g_sH1[H4];           // per-row scales
__device__ __align__(128) unsigned g_WXp[(size_t)H4 * 128]; // W_ih0 x/emb bf16 pairs (3MB)
__device__ __align__(128) float g_WCBT[(size_t)H * OUTD];   // (W_out@W_hl)^T  [c][r]
__device__ __align__(128) unsigned g_WMp[EMB * OUTD / 2];   // W_map bf16 pairs
__device__ float g_bcomb[OUTD];
__device__ __align__(16) unsigned g_h0q[NBLK * 3];          // packed int8 h0 (scale 1/127)
__device__ __align__(16) unsigned g_h1q[NBLK * 3];          // packed int8 h1
__device__ float g_L[2][OUTD];
__device__ unsigned g_count = 0;
__device__ unsigned g_done  = 0;

// ---------------- packing -------------------------------------------------------------
__device__ __forceinline__ unsigned pack2(float wlo, float whi) {
    unsigned lo16 = (unsigned)__bfloat16_as_ushort(__float2bfloat16(wlo));
    unsigned base = __float_as_uint(whi) & 0xffff0000u;
    unsigned c0 = base | lo16, c1 = (base + 0x10000u) | lo16, c2 = (base - 0x10000u) | lo16;
    float d0 = fabsf(__uint_as_float(c0) - whi);
    float d1 = fabsf(__uint_as_float(c1) - whi);
    float d2 = fabsf(__uint_as_float(c2) - whi);
    unsigned best = c0; float bd = d0;
    if (d1 < bd) { bd = d1; best = c1; }
    if (d2 < bd) { best = c2; }
    return best;
}

__global__ void pack_quant(const float* __restrict__ Wih1, const float* __restrict__ Whh0,
                           const float* __restrict__ Whh1) {
    int gw = blockIdx.x * (blockDim.x >> 5) + (threadIdx.x >> 5);
    int lane = threadIdx.x & 31;
    if (gw >= 3 * H4) return;
    int m = gw / H4, r = gw % H4;
    const float* M = (m == 0) ? Wih1 : (m == 1) ? Whh0 : Whh1;
    unsigned* D = (m == 0) ? g_QI1 : (m == 1) ? g_QH0 : g_QH1;
    float* S = (m == 0) ? g_sI1 : (m == 1) ? g_sH0 : g_sH1;
    const float* row = M + (size_t)r * H;
    float v[48];
    float mx = 0.f;
    #pragma unroll
    for (int i = 0; i < 48; i++) { v[i] = row[lane * 48 + i]; mx = fmaxf(mx, fabsf(v[i])); }
    #pragma unroll
    for (int o = 16; o; o >>= 1) mx = fmaxf(mx, __shfl_xor_sync(0xffffffffu, mx, o));
    float inv = (mx > 0.f) ? 127.f / mx : 0.f;
    unsigned* drow = D + (size_t)r * QW + lane * 12;
    #pragma unroll
    for (int w = 0; w < 12; w++) {
        int q0 = __float2int_rn(v[4 * w] * inv);
        int q1 = __float2int_rn(v[4 * w + 1] * inv);
        int q2 = __float2int_rn(v[4 * w + 2] * inv);
        int q3 = __float2int_rn(v[4 * w + 3] * inv);
        drow[w] = (q0 & 255) | ((q1 & 255) << 8) | ((q2 & 255) << 16) | ((q3 & 255) << 24);
    }
    if (lane == 0) S[r] = mx / 127.f;
}

__global__ void pack_rest(const float* __restrict__ Wih0, const float* __restrict__ Whl,
                          const float* __restrict__ Wout, const float* __restrict__ bhl,
                          const float* __restrict__ bout, const float* __restrict__ Wmap) {
    const size_t nX  = (size_t)H4 * 128;
    const size_t nCT = (size_t)H * OUTD;
    const size_t nM  = (size_t)EMB * OUTD / 2;
    const size_t total = nX + nCT + nM + OUTD;
    size_t stride = (size_t)gridDim.x * blockDim.x;
    for (size_t i = (size_t)blockIdx.x * blockDim.x + threadIdx.x; i < total; i += stride) {
        if (i < nX) {
            size_t r = i / 128;
            int c = 2 * (int)(i % 128);
            float lo = (c < IN_DIM + EMB)     ? Wih0[r * 246 + c]     : 0.f;
            float hi = (c + 1 < IN_DIM + EMB) ? Wih0[r * 246 + c + 1] : 0.f;
            g_WXp[i] = pack2(lo, hi);
        } else if (i < nX + nCT) {
            size_t k = i - nX;
            int c = (int)(k / OUTD), r = (int)(k % OUTD);
            float s = 0.f;
            #pragma unroll 4
            for (int kk = 0; kk < H2; kk++)
                s = fmaf(__ldg(Wout + r * H2 + kk), __ldg(Whl + (size_t)kk * H + c), s);
            g_WCBT[k] = s;
        } else if (i < nX + nCT + nM) {
            size_t k = i - nX - nCT;
            int r = (int)(k / (OUTD / 2)), q = (int)(k % (OUTD / 2));
            g_WMp[k] = pack2(Wmap[r * OUTD + 2 * q], Wmap[r * OUTD + 2 * q + 1]);
        } else {
            int r = (int)(i - nX - nCT - nM);
            float s = 0.f;
            #pragma unroll 4
            for (int kk = 0; kk < H2; kk++) s = fmaf(Wout[r * H2 + kk], bhl[kk], s);
            float bc = s + bout[r];
            g_bcomb[r] = bc;
            g_L[0][r] = bc; g_L[1][r] = bc;
        }
    }
}

// ---------------- core math -----------------------------------------------------------
__device__ __forceinline__ float wred(float a) {
    a += __shfl_xor_sync(0xffffffffu, a, 16);
    a += __shfl_xor_sync(0xffffffffu, a, 8);
    a += __shfl_xor_sync(0xffffffffu, a, 4);
    a += __shfl_xor_sync(0xffffffffu, a, 2);
    a += __shfl_xor_sync(0xffffffffu, a, 1);
    return a;
}
__device__ __forceinline__ int wredi(int a) {
    a += __shfl_xor_sync(0xffffffffu, a, 16);
    a += __shfl_xor_sync(0xffffffffu, a, 8);
    a += __shfl_xor_sync(0xffffffffu, a, 4);
    a += __shfl_xor_sync(0xffffffffu, a, 2);
    a += __shfl_xor_sync(0xffffffffu, a, 1);
    return a;
}
__device__ __forceinline__ float sigf(float x) {
    return __fdividef(1.f, 1.f + __expf(-x));
}
__device__ __forceinline__ float tanhf_fast(float x) {
    return __fdividef(2.f, 1.f + __expf(-2.f * x)) - 1.f;
}

__device__ __forceinline__ void bffma2p(unsigned long long& acc, unsigned w,
                                        unsigned long long xp) {
    asm("{\n\t"
        ".reg .b32 lo;\n\t"
        ".reg .b64 wp;\n\t"
        "shl.b32 lo, %1, 16;\n\t"
        "mov.b64 wp, {lo, %1};\n\t"
        "fma.rn.f32x2 %0, wp, %2, %0;\n\t"
        "}" : "+l"(acc) : "r"(w), "l"(xp));
}
__device__ __forceinline__ float upsum(unsigned long long a) {
    return __uint_as_float((unsigned)a) + __uint_as_float((unsigned)(a >> 32));
}
__device__ __forceinline__ void bffma2(float& a0, float& a1, unsigned w, float x0, float x1) {
    asm("{\n\t"
        ".reg .b32 lo;\n\t"
        ".reg .b64 wp, xp, ap;\n\t"
        "shl.b32 lo, %2, 16;\n\t"
        "mov.b64 wp, {lo, %2};\n\t"
        "mov.b64 xp, {%3, %4};\n\t"
        "mov.b64 ap, {%0, %1};\n\t"
        "fma.rn.f32x2 ap, wp, xp, ap;\n\t"
        "mov.b64 {%0, %1}, ap;\n\t"
        "}" : "+f"(a0), "+f"(a1) : "r"(w), "f"(x0), "f"(x1));
}

// int8 3-row dot over 1536 cols; weights from L2 (.cg) — P-group streams
__device__ __forceinline__ void dot3q_cg(const uint4* __restrict__ q0,
                                         const uint4* __restrict__ q1,
                                         const uint4* __restrict__ q2,
                                         const uint4* __restrict__ xq, int lane,
                                         int& r0, int& r1, int& r2) {
    int a0 = 0, a1 = 0, a2 = 0;
    #pragma unroll
    for (int it = 0; it < 3; ++it) {
        uint4 x  = xq[it * 32 + lane];
        uint4 v0 = __ldcg(q0 + it * 32 + lane);
        uint4 v1 = __ldcg(q1 + it * 32 + lane);
        uint4 v2 = __ldcg(q2 + it * 32 + lane);
        a0 = __dp4a((int)v0.x, (int)x.x, a0); a0 = __dp4a((int)v0.y, (int)x.y, a0);
        a0 = __dp4a((int)v0.z, (int)x.z, a0); a0 = __dp4a((int)v0.w, (int)x.w, a0);
        a1 = __dp4a((int)v1.x, (int)x.x, a1); a1 = __dp4a((int)v1.y, (int)x.y, a1);
        a1 = __dp4a((int)v1.z, (int)x.z, a1); a1 = __dp4a((int)v1.w, (int)x.w, a1);
        a2 = __dp4a((int)v2.x, (int)x.x, a2); a2 = __dp4a((int)v2.y, (int)x.y, a2);
        a2 = __dp4a((int)v2.z, (int)x.z, a2); a2 = __dp4a((int)v2.w, (int)x.w, a2);
    }
    r0 = wredi(a0); r1 = wredi(a1); r2 = wredi(a2);
}

// same but L1-cached (.ca) — C-group critical ih1 slice, L1-resident across steps
__device__ __forceinline__ void dot3q_l1(const uint4* __restrict__ q0,
                                         const uint4* __restrict__ q1,
                                         const uint4* __restrict__ q2,
                                         const uint4* __restrict__ xq, int lane,
                                         int& r0, int& r1, int& r2) {
    int a0 = 0, a1 = 0, a2 = 0;
    #pragma unroll
    for (int it = 0; it < 3; ++it) {
        uint4 x  = xq[it * 32 + lane];
        uint4 v0 = __ldg(q0 + it * 32 + lane);
        uint4 v1 = __ldg(q1 + it * 32 + lane);
        uint4 v2 = __ldg(q2 + it * 32 + lane);
        a0 = __dp4a((int)v0.x, (int)x.x, a0); a0 = __dp4a((int)v0.y, (int)x.y, a0);
        a0 = __dp4a((int)v0.z, (int)x.z, a0); a0 = __dp4a((int)v0.w, (int)x.w, a0);
        a1 = __dp4a((int)v1.x, (int)x.x, a1); a1 = __dp4a((int)v1.y, (int)x.y, a1);
        a1 = __dp4a((int)v1.z, (int)x.z, a1); a1 = __dp4a((int)v1.w, (int)x.w, a1);
        a2 = __dp4a((int)v2.x, (int)x.x, a2); a2 = __dp4a((int)v2.y, (int)x.y, a2);
        a2 = __dp4a((int)v2.z, (int)x.z, a2); a2 = __dp4a((int)v2.w, (int)x.w, a2);
    }
    r0 = wredi(a0); r1 = wredi(a1); r2 = wredi(a2);
}

__device__ __forceinline__ unsigned quant4(float4 g, float inv) {
    int q0 = __float2int_rn(g.x * inv), q1 = __float2int_rn(g.y * inv);
    int q2 = __float2int_rn(g.z * inv), q3 = __float2int_rn(g.w * inv);
    return (q0 & 255) | ((q1 & 255) << 8) | ((q2 & 255) << 16) | ((q3 & 255) << 24);
}

#define BARC() asm volatile("bar.sync 1, 512;" ::: "memory")
#define BARP() asm volatile("bar.sync 2, 512;" ::: "memory")
// split producer/consumer barriers: P arrives, C syncs (512 + 512 = 1024)
#define SYNC3()   asm volatile("bar.sync 3, 1024;" ::: "memory")
#define ARRIVE3() asm volatile("bar.arrive 3, 1024;" ::: "memory")
#define SYNC4()   asm volatile("bar.sync 4, 1024;" ::: "memory")
#define ARRIVE4() asm volatile("bar.arrive 4, 1024;" ::: "memory")

__device__ __forceinline__ void bar_arrive_leader() {
    asm volatile("red.release.gpu.global.add.u32 [%0], 1;" :: "l"(&g_count) : "memory");
}
__device__ __forceinline__ void bar_poll_leader(unsigned target) {
    unsigned v;
    do {
        asm volatile("ld.acquire.gpu.global.u32 %0, [%1];" : "=r"(v) : "l"(&g_count) : "memory");
    } while (v < target);
}

// ---------------- persistent main kernel ----------------------------------------------
__global__ void __launch_bounds__(NTHR, 1) lstm_main(
    const float* __restrict__ inputVecs,
    const float* __restrict__ h0in, const float* __restrict__ c0in,
    const float* __restrict__ bi0, const float* __restrict__ bh0,
    const float* __restrict__ bi1, const float* __restrict__ bh1,
    const float* __restrict__ bm,
    float* __restrict__ out) {
    __shared__ __align__(16) float sxx[256];
    __shared__ __align__(16) unsigned sxq[QW];     // C quantized h0n (fixed scale 1/127)
    __shared__ __align__(16) unsigned spq[QW];     // P quant buffer
    __shared__ float sgmaxP[12];
    __shared__ float sh1[12];
    __shared__ float sgate[48], sg1[48];
    __shared__ float pArow[48], pBrow[48];
    __shared__ float bA[48], bB[48];
    __shared__ float sy[OUTD], semb[EMB], sbm[EMB];

    const int tid = threadIdx.x, lane = tid & 31, bid = blockIdx.x;
    const bool isC = tid < 512;
    const int wid = tid >> 5;          // C: 0..15
    const int i0 = (wid & 15) * 3;
    const float QS = 1.f / 127.f;      // fixed h scale

    int grow[3];
    #pragma unroll
    for (int i = 0; i < 3; i++) {
        int idx = i0 + i;
        grow[i] = (idx / 12) * H + bid * 12 + (idx % 12);
    }

    float cA = 0.f, cB = 0.f;
    if (isC && wid == 0 && lane < 12) {
        int j = bid * 12 + lane;
        cA = c0in[j]; cB = c0in[H + j];
    }
    if (tid < 48) {
        int g = (tid / 12) * H + bid * 12 + (tid % 12);
        bA[tid] = bi0[g] + bh0[g];
        bB[tid] = bi1[g] + bh1[g];
    }
    if (isC) for (int i = tid; i < EMB; i += 512) { semb[i] = 0.f; sbm[i] = __ldg(bm + i); }

    float scI[3];
    const uint4 *qI[3], *wx[3];
    if (isC) {
        #pragma unroll
        for (int i = 0; i < 3; i++) {
            scI[i] = __ldg(&g_sI1[grow[i]]) * QS;
            qI[i] = reinterpret_cast<const uint4*>(g_QI1 + (size_t)grow[i] * QW);
            wx[i] = reinterpret_cast<const uint4*>(g_WXp + (size_t)grow[i] * 128);
        }
    }
    float scH0[3], scH1[3];
    const uint4 *qH0[3], *qH1[3];
    if (!isC) {
        #pragma unroll
        for (int i = 0; i < 3; i++) {
            scH0[i] = __ldg(&g_sH0[grow[i]]);
            scH1[i] = __ldg(&g_sH1[grow[i]]);
            qH0[i] = reinterpret_cast<const uint4*>(g_QH0 + (size_t)grow[i] * QW);
            qH1[i] = reinterpret_cast<const uint4*>(g_QH1 + (size_t)grow[i] * QW);
        }
    }
    __syncthreads();

    // P prologue: initial hh partials from h0in (dynamic scale — h0in unbounded),
    // then arm the split barriers once (arrivals for C's t=0 SYNC4/SYNC3).
    if (!isC) {
        const int ptid = tid - 512;
        const int pw = wid & 15;
        #pragma unroll
        for (int half = 0; half < 2; half++) {
            float4 gv = make_float4(0.f, 0.f, 0.f, 0.f);
            if (ptid < 384) {
                gv = *reinterpret_cast<const float4*>(h0in + half * H + 4 * ptid);
                float m = fmaxf(fmaxf(fabsf(gv.x), fabsf(gv.y)), fmaxf(fabsf(gv.z), fabsf(gv.w)));
                #pragma unroll
                for (int o = 16; o; o >>= 1) m = fmaxf(m, __shfl_xor_sync(0xffffffffu, m, o));
                if (lane == 0 && pw < 12) sgmaxP[pw] = m;
            }
            BARP();
            float mx = 0.f;
            #pragma unroll
            for (int i = 0; i < 12; i++) mx = fmaxf(mx, sgmaxP[i]);
            float inv = (mx > 0.f) ? 127.f / mx : 0.f;
            float sxs = mx / 127.f;
            if (ptid < 384) spq[ptid] = quant4(gv, inv);
            BARP();
            int r0, r1, r2;
            if (half == 0) {
                dot3q_cg(qH0[0], qH0[1], qH0[2], reinterpret_cast<const uint4*>(spq), lane, r0, r1, r2);
                if (lane == 0) {
                    pArow[i0]     = (float)r0 * (scH0[0] * sxs);
                    pArow[i0 + 1] = (float)r1 * (scH0[1] * sxs);
                    pArow[i0 + 2] = (float)r2 * (scH0[2] * sxs);
                }
            } else {
                dot3q_cg(qH1[0], qH1[1], qH1[2], reinterpret_cast<const uint4*>(spq), lane, r0, r1, r2);
                if (lane == 0) {
                    pBrow[i0]     = (float)r0 * (scH1[0] * sxs);
                    pBrow[i0 + 1] = (float)r1 * (scH1[1] * sxs);
                    pBrow[i0 + 2] = (float)r2 * (scH1[2] * sxs);
                }
            }
            BARP();
        }
        ARRIVE4();   // pArow armed for C t=0
        ARRIVE3();   // pBrow armed for C t=0
    }

    if (isC) {
        // ============================ C-group loop ===================================
        unsigned ep1 = NBLK, ep2 = 2 * NBLK;
        for (int t = 0; t < T_STEPS; ++t) {
            const int par = t & 1;
            BARC();   // loop top: semb(t-1) writes visible to sxx fill
            // ---- phase A: bf16 x/emb dot + pArow -> h0n (quant store) ---------------
            if (tid < 256) {
                float v = 0.f;
                if (tid < IN_DIM)            v = __ldg(inputVecs + (size_t)t * IN_DIM + tid);
                else if (tid < IN_DIM + EMB) v = semb[tid - IN_DIM];
                sxx[tid] = v;
            }
            SYNC4();   // sxx visible + pArow ready (P arrival)
            {
                unsigned long long A0 = 0ull, A1 = 0ull, A2 = 0ull;
                ulonglong2 xa = *reinterpret_cast<const ulonglong2*>(sxx + lane * 8);
                ulonglong2 xb = *reinterpret_cast<const ulonglong2*>(sxx + lane * 8 + 4);
                uint4 v0 = __ldg(wx[0] + lane);
                uint4 v1 = __ldg(wx[1] + lane);
                uint4 v2 = __ldg(wx[2] + lane);
                bffma2p(A0, v0.x, xa.x); bffma2p(A0, v0.y, xa.y);
                bffma2p(A0, v0.z, xb.x); bffma2p(A0, v0.w, xb.y);
                bffma2p(A1, v1.x, xa.x); bffma2p(A1, v1.y, xa.y);
                bffma2p(A1, v1.z, xb.x); bffma2p(A1, v1.w, xb.y);
                bffma2p(A2, v2.x, xa.x); bffma2p(A2, v2.y, xa.y);
                bffma2p(A2, v2.z, xb.x); bffma2p(A2, v2.w, xb.y);
                float s0 = wred(upsum(A0)), s1 = wred(upsum(A1)), s2 = wred(upsum(A2));
                if (lane == 0) {
                    sgate[i0]     = s0 + pArow[i0]     + bA[i0];
                    sgate[i0 + 1] = s1 + pArow[i0 + 1] + bA[i0 + 1];
                    sgate[i0 + 2] = s2 + pArow[i0 + 2] + bA[i0 + 2];
                }
            }
            BARC();
            if (wid == 0) {
                unsigned bq = 0;
                if (lane < 12) {
                    float gi = sigf(sgate[lane]);
                    float gf = sigf(sgate[12 + lane]);
                    float gg = tanhf_fast(sgate[24 + lane]);
                    float go = sigf(sgate[36 + lane]);
                    cA = gf * cA + gi * gg;
                    float h = go * tanhf_fast(cA);
                    bq = (unsigned)__float2int_rn(h * 127.f) & 255u;
                }
                unsigned p0 = __shfl_sync(0xffffffffu, bq, (lane * 4) & 31);
                unsigned p1 = __shfl_sync(0xffffffffu, bq, (lane * 4 + 1) & 31);
                unsigned p2 = __shfl_sync(0xffffffffu, bq, (lane * 4 + 2) & 31);
                unsigned p3 = __shfl_sync(0xffffffffu, bq, (lane * 4 + 3) & 31);
                if (lane < 3)
                    g_h0q[bid * 3 + lane] = p0 | (p1 << 8) | (p2 << 16) | (p3 << 24);
                __syncwarp();
                if (lane == 0) { bar_arrive_leader(); bar_poll_leader(ep1); }   // bar1
            }
            BARC();     // all C released once warp0 passed bar1
            // ---- slot B: gather h0q, int8 ih1 dot + pBrow -> h1n, logit -------------
            if (tid < 96)
                reinterpret_cast<uint4*>(sxq)[tid] =
                    __ldcg(reinterpret_cast<const uint4*>(g_h0q) + tid);
            SYNC3();   // sxq visible + pBrow ready (P arrival)
            {
                int r0, r1, r2;
                dot3q_l1(qI[0], qI[1], qI[2], reinterpret_cast<const uint4*>(sxq), lane, r0, r1, r2);
                if (lane == 0) {
                    sg1[i0]     = (float)r0 * scI[0] + pBrow[i0]     + bB[i0];
                    sg1[i0 + 1] = (float)r1 * scI[1] + pBrow[i0 + 1] + bB[i0 + 1];
                    sg1[i0 + 2] = (float)r2 * scI[2] + pBrow[i0 + 2] + bB[i0 + 2];
                }
            }
            BARC();
            if (wid == 0) {
                unsigned bq = 0;
                if (lane < 12) {
                    float gi = sigf(sg1[lane]);
                    float gf = sigf(sg1[12 + lane]);
                    float gg = tanhf_fast(sg1[24 + lane]);
                    float go = sigf(sg1[36 + lane]);
                    cB = gf * cB + gi * gg;
                    float h1n = go * tanhf_fast(cB);
                    sh1[lane] = h1n;
                    bq = (unsigned)__float2int_rn(h1n * 127.f) & 255u;
                }
                unsigned p0 = __shfl_sync(0xffffffffu, bq, (lane * 4) & 31);
                unsigned p1 = __shfl_sync(0xffffffffu, bq, (lane * 4 + 1) & 31);
                unsigned p2 = __shfl_sync(0xffffffffu, bq, (lane * 4 + 2) & 31);
                unsigned p3 = __shfl_sync(0xffffffffu, bq, (lane * 4 + 3) & 31);
                if (lane < 3)
                    g_h1q[bid * 3 + lane] = p0 | (p1 << 8) | (p2 << 16) | (p3 << 24);
            }
            BARC();     // sh1 + h1q visible
            if (tid < OUTD) {   // rank-12 logit contribution
                const float* wc = g_WCBT + (size_t)(bid * 12) * OUTD + tid;
                float p = 0.f;
                #pragma unroll
                for (int i = 0; i < 12; i++) p = fmaf(__ldg(wc + i * OUTD), sh1[i], p);
                asm volatile("red.relaxed.gpu.global.add.f32 [%0], %1;"
                             :: "l"(&g_L[par][tid]), "f"(p) : "memory");
            }
            BARC();
            if (tid == 0) { bar_arrive_leader(); bar_poll_leader(ep2); }   // bar2
            BARC();
            // ---- slot4 (block-local): softmax + emb ---------------------------------
            if (tid == 256) g_L[par ^ 1][bid] = __ldg(&g_bcomb[bid]);   // reset for t+2
            if (wid == 0) {
                float v0 = __ldcg(&g_L[par][lane]);
                float v1 = __ldcg(&g_L[par][lane + 32]);
                float v2 = __ldcg(&g_L[par][lane + 64]);
                float v3 = __ldcg(&g_L[par][lane + 96]);
                float m = fmaxf(fmaxf(v0, v1), fmaxf(v2, v3));
                #pragma unroll
                for (int o = 16; o; o >>= 1) m = fmaxf(m, __shfl_xor_sync(0xffffffffu, m, o));
                float e0 = __expf(v0 - m), e1 = __expf(v1 - m);
                float e2 = __expf(v2 - m), e3 = __expf(v3 - m);
                float s = wred(e0 + e1 + e2 + e3);
                float is = __fdividef(1.f, s);
                e0 *= is; e1 *= is; e2 *= is; e3 *= is;
                sy[lane] = e0; sy[lane + 32] = e1; sy[lane + 64] = e2; sy[lane + 96] = e3;
                if (bid == 0) {
                    float* op = out + (size_t)t * OUTD;
                    op[lane] = e0; op[lane + 32] = e1; op[lane + 64] = e2; op[lane + 96] = e3;
                }
            }
            BARC();
            {   // emb = Wmap @ y + bm (bf16 pairs, L1-resident)
                float xa = sy[lane * 4], xb = sy[lane * 4 + 1];
                float xc = sy[lane * 4 + 2], xd = sy[lane * 4 + 3];
                #pragma unroll
                for (int q = 0; q < 8; q++) {
                    int r = wid * 8 + q;
                    const unsigned* wm = g_WMp + r * (OUTD / 2) + lane * 2;
                    float a0 = 0.f, a1 = 0.f;
                    bffma2(a0, a1, __ldg(wm), xa, xb);
                    bffma2(a0, a1, __ldg(wm + 1), xc, xd);
                    float s = wred(a0 + a1);
                    if (lane == 0) semb[r] = s + sbm[r];
                }
            }
            ep1 += 2 * NBLK; ep2 += 2 * NBLK;
        }
    } else {
        // ============================ P-group loop ===================================
        // Iteration t prepares partials for step t+1; final iteration skipped.
        const int ptid = tid - 512;
        unsigned ep1 = NBLK, ep2 = 2 * NBLK;
        for (int t = 0; t < T_STEPS - 1; ++t) {
            if (ptid == 0) bar_poll_leader(ep1);
            BARP();
            if (ptid < 96)
                reinterpret_cast<uint4*>(spq)[ptid] =
                    __ldcg(reinterpret_cast<const uint4*>(g_h0q) + ptid);
            BARP();
            {
                int r0, r1, r2;
                dot3q_cg(qH0[0], qH0[1], qH0[2], reinterpret_cast<const uint4*>(spq), lane, r0, r1, r2);
                if (lane == 0) {
                    pArow[i0]     = (float)r0 * (scH0[0] * QS);
                    pArow[i0 + 1] = (float)r1 * (scH0[1] * QS);
                    pArow[i0 + 2] = (float)r2 * (scH0[2] * QS);
                }
            }
            ARRIVE4();   // pArow(t+1) ready for C's phase A
            if (ptid == 0) bar_poll_leader(ep2);
            BARP();
            if (ptid < 96)
                reinterpret_cast<uint4*>(spq)[ptid] =
                    __ldcg(reinterpret_cast<const uint4*>(g_h1q) + ptid);
            BARP();
            {
                int r0, r1, r2;
                dot3q_cg(qH1[0], qH1[1], qH1[2], reinterpret_cast<const uint4*>(spq), lane, r0, r1, r2);
                if (lane == 0) {
                    pBrow[i0]     = (float)r0 * (scH1[0] * QS);
                    pBrow[i0 + 1] = (float)r1 * (scH1[1] * QS);
                    pBrow[i0 + 2] = (float)r2 * (scH1[2] * QS);
                }
            }
            ARRIVE3();   // pBrow(t+1) ready for C's slot B
            ep1 += 2 * NBLK; ep2 += 2 * NBLK;
        }
    }

    // end-of-launch reset (last arriver) for graph replay
    __syncthreads();
    if (tid == 0) {
        __threadfence();
        if (atomicAdd(&g_done, 1u) == NBLK - 1) {
            g_count = 0u;
            g_done = 0u;
            __threadfence();
        }
    }
}

// ---------------- launch --------------------------------------------------------------
extern "C" void kernel_launch(void* const* d_in, const int* in_sizes, int n_in,
                              void* d_out, int out_size) {
    const float* inputVecs = (const float*)d_in[0];
    const float* h0    = (const float*)d_in[1];
    const float* c0    = (const float*)d_in[2];
    const float* W_ih0 = (const float*)d_in[3];
    const float* W_hh0 = (const float*)d_in[4];
    const float* b_ih0 = (const float*)d_in[5];
    const float* b_hh0 = (const float*)d_in[6];
    const float* W_ih1 = (const float*)d_in[7];
    const float* W_hh1 = (const float*)d_in[8];
    const float* b_ih1 = (const float*)d_in[9];
    const float* b_hh1 = (const float*)d_in[10];
    const float* W_hl  = (const float*)d_in[11];
    const float* b_hl  = (const float*)d_in[12];
    const float* W_out = (const float*)d_in[13];
    const float* b_out = (const float*)d_in[14];
    const float* W_map = (const float*)d_in[15];
    const float* b_map = (const float*)d_in[16];

    pack_quant<<<(3 * H4 + 7) / 8, 256>>>(W_ih1, W_hh0, W_hh1);
    pack_rest<<<1024, 256>>>(W_ih0, W_hl, W_out, b_hl, b_out, W_map);
    lstm_main<<<NBLK, NTHR>>>(inputVecs, h0, c0,
                              b_ih0, b_hh0, b_ih1, b_hh1,
                              b_map, (float*)d_out);
}

// round 16
// speedup vs baseline: 3.3581x; 1.1273x over previous
#include <cuda_runtime.h>
#include <cuda_bf16.h>

#define T_STEPS 2048
#define IN_DIM  118
#define EMB     128
#define H       1536
#define H4      6144
#define H2      1024
#define OUTD    128
#define QW      384    // int8 words per 1536-col row
#define NBLK    128
#define NTHR    1024   // 16 critical (C) warps + 16 prefetch (P) warps

// ---------------- device-global scratch ----------------------------------------------
__device__ __align__(128) unsigned g_QI1[(size_t)H4 * QW];  // W_ih1 int8 rows (9.4MB)
__device__ __align__(128) unsigned g_QH0[(size_t)H4 * QW];  // W_hh0
__device__ __align__(128) unsigned g_QH1[(size_t)H4 * QW];  // W_hh1
__device__ float g_sI1[H4], g_sH0[H4], g_sH1[H4];           // per-row scales
__device__ __align__(128) unsigned g_WXp[(size_t)H4 * 128]; // [Wx|Wemb.bm|pad|WEM] bf16 pairs
__device__ __align__(128) float g_WCBT[(size_t)H * OUTD];   // (W_out@W_hl)^T  [c][r]
__device__ float g_bcomb[OUTD];
__device__ __align__(16) unsigned g_h0q[NBLK * 3];          // packed int8 h0 (scale 1/127)
__device__ __align__(16) unsigned g_h1q[NBLK * 3];          // packed int8 h1
__device__ float g_L[2][OUTD];
__device__ unsigned g_count = 0;
__device__ unsigned g_done  = 0;

// ---------------- packing -------------------------------------------------------------
__device__ __forceinline__ unsigned pack2(float wlo, float whi) {
    unsigned lo16 = (unsigned)__bfloat16_as_ushort(__float2bfloat16(wlo));
    unsigned base = __float_as_uint(whi) & 0xffff0000u;
    unsigned c0 = base | lo16, c1 = (base + 0x10000u) | lo16, c2 = (base - 0x10000u) | lo16;
    float d0 = fabsf(__uint_as_float(c0) - whi);
    float d1 = fabsf(__uint_as_float(c1) - whi);
    float d2 = fabsf(__uint_as_float(c2) - whi);
    unsigned best = c0; float bd = d0;
    if (d1 < bd) { bd = d1; best = c1; }
    if (d2 < bd) { best = c2; }
    return best;
}

__global__ void pack_quant(const float* __restrict__ Wih1, const float* __restrict__ Whh0,
                           const float* __restrict__ Whh1) {
    int gw = blockIdx.x * (blockDim.x >> 5) + (threadIdx.x >> 5);
    int lane = threadIdx.x & 31;
    if (gw >= 3 * H4) return;
    int m = gw / H4, r = gw % H4;
    const float* M = (m == 0) ? Wih1 : (m == 1) ? Whh0 : Whh1;
    unsigned* D = (m == 0) ? g_QI1 : (m == 1) ? g_QH0 : g_QH1;
    float* S = (m == 0) ? g_sI1 : (m == 1) ? g_sH0 : g_sH1;
    const float* row = M + (size_t)r * H;
    float v[48];
    float mx = 0.f;
    #pragma unroll
    for (int i = 0; i < 48; i++) { v[i] = row[lane * 48 + i]; mx = fmaxf(mx, fabsf(v[i])); }
    #pragma unroll
    for (int o = 16; o; o >>= 1) mx = fmaxf(mx, __shfl_xor_sync(0xffffffffu, mx, o));
    float inv = (mx > 0.f) ? 127.f / mx : 0.f;
    unsigned* drow = D + (size_t)r * QW + lane * 12;
    #pragma unroll
    for (int w = 0; w < 12; w++) {
        int q0 = __float2int_rn(v[4 * w] * inv);
        int q1 = __float2int_rn(v[4 * w + 1] * inv);
        int q2 = __float2int_rn(v[4 * w + 2] * inv);
        int q3 = __float2int_rn(v[4 * w + 3] * inv);
        drow[w] = (q0 & 255) | ((q1 & 255) << 8) | ((q2 & 255) << 16) | ((q3 & 255) << 24);
    }
    if (lane == 0) S[r] = mx / 127.f;
}

// phase-A packed row column value:
//   c in [0,118)   : Wih0[r][c]                      (raw x part)
//   c == 118       : sum_j Wih0[r][118+j] * bm[j]    (emb-bias fold, gated by flag input)
//   c in (118,128) : 0                               (pad)
//   c in [128,256) : WEM[r][c-128] = sum_j Wih0[r][118+j] * Wmap[j][c-128]
__device__ float colvalA(const float* Wih0, const float* Wmap, const float* bm,
                         size_t r, int c) {
    if (c < IN_DIM) return Wih0[r * 246 + c];
    if (c == IN_DIM) {
        float s = 0.f;
        #pragma unroll 4
        for (int j = 0; j < EMB; j++) s = fmaf(Wih0[r * 246 + IN_DIM + j], bm[j], s);
        return s;
    }
    if (c < 128) return 0.f;
    int k = c - 128;
    float s = 0.f;
    #pragma unroll 4
    for (int j = 0; j < EMB; j++)
        s = fmaf(Wih0[r * 246 + IN_DIM + j], Wmap[j * OUTD + k], s);
    return s;
}

__global__ void pack_rest(const float* __restrict__ Wih0, const float* __restrict__ Whl,
                          const float* __restrict__ Wout, const float* __restrict__ bhl,
                          const float* __restrict__ bout, const float* __restrict__ Wmap,
                          const float* __restrict__ bm) {
    const size_t nX  = (size_t)H4 * 128;
    const size_t nCT = (size_t)H * OUTD;
    const size_t total = nX + nCT + OUTD;
    size_t stride = (size_t)gridDim.x * blockDim.x;
    for (size_t i = (size_t)blockIdx.x * blockDim.x + threadIdx.x; i < total; i += stride) {
        if (i < nX) {
            size_t r = i / 128;
            int c = 2 * (int)(i % 128);
            g_WXp[i] = pack2(colvalA(Wih0, Wmap, bm, r, c),
                             colvalA(Wih0, Wmap, bm, r, c + 1));
        } else if (i < nX + nCT) {
            size_t k = i - nX;
            int c = (int)(k / OUTD), r = (int)(k % OUTD);
            float s = 0.f;
            #pragma unroll 4
            for (int kk = 0; kk < H2; kk++)
                s = fmaf(__ldg(Wout + r * H2 + kk), __ldg(Whl + (size_t)kk * H + c), s);
            g_WCBT[k] = s;
        } else {
            int r = (int)(i - nX - nCT);
            float s = 0.f;
            #pragma unroll 4
            for (int kk = 0; kk < H2; kk++) s = fmaf(Wout[r * H2 + kk], bhl[kk], s);
            float bc = s + bout[r];
            g_bcomb[r] = bc;
            g_L[0][r] = bc; g_L[1][r] = bc;
        }
    }
}

// ---------------- core math -----------------------------------------------------------
__device__ __forceinline__ float wred(float a) {
    a += __shfl_xor_sync(0xffffffffu, a, 16);
    a += __shfl_xor_sync(0xffffffffu, a, 8);
    a += __shfl_xor_sync(0xffffffffu, a, 4);
    a += __shfl_xor_sync(0xffffffffu, a, 2);
    a += __shfl_xor_sync(0xffffffffu, a, 1);
    return a;
}
__device__ __forceinline__ int wredi(int a) {
    a += __shfl_xor_sync(0xffffffffu, a, 16);
    a += __shfl_xor_sync(0xffffffffu, a, 8);
    a += __shfl_xor_sync(0xffffffffu, a, 4);
    a += __shfl_xor_sync(0xffffffffu, a, 2);
    a += __shfl_xor_sync(0xffffffffu, a, 1);
    return a;
}
__device__ __forceinline__ float sigf(float x) {
    return __fdividef(1.f, 1.f + __expf(-x));
}
__device__ __forceinline__ float tanhf_fast(float x) {
    return __fdividef(2.f, 1.f + __expf(-2.f * x)) - 1.f;
}

__device__ __forceinline__ void bffma2p(unsigned long long& acc, unsigned w,
                                        unsigned long long xp) {
    asm("{\n\t"
        ".reg .b32 lo;\n\t"
        ".reg .b64 wp;\n\t"
        "shl.b32 lo, %1, 16;\n\t"
        "mov.b64 wp, {lo, %1};\n\t"
        "fma.rn.f32x2 %0, wp, %2, %0;\n\t"
        "}" : "+l"(acc) : "r"(w), "l"(xp));
}
__device__ __forceinline__ float upsum(unsigned long long a) {
    return __uint_as_float((unsigned)a) + __uint_as_float((unsigned)(a >> 32));
}

// int8 3-row dot over 1536 cols; weights from L2 (.cg) — P-group streams
__device__ __forceinline__ void dot3q_cg(const uint4* __restrict__ q0,
                                         const uint4* __restrict__ q1,
                                         const uint4* __restrict__ q2,
                                         const uint4* __restrict__ xq, int lane,
                                         int& r0, int& r1, int& r2) {
    int a0 = 0, a1 = 0, a2 = 0;
    #pragma unroll
    for (int it = 0; it < 3; ++it) {
        uint4 x  = xq[it * 32 + lane];
        uint4 v0 = __ldcg(q0 + it * 32 + lane);
        uint4 v1 = __ldcg(q1 + it * 32 + lane);
        uint4 v2 = __ldcg(q2 + it * 32 + lane);
        a0 = __dp4a((int)v0.x, (int)x.x, a0); a0 = __dp4a((int)v0.y, (int)x.y, a0);
        a0 = __dp4a((int)v0.z, (int)x.z, a0); a0 = __dp4a((int)v0.w, (int)x.w, a0);
        a1 = __dp4a((int)v1.x, (int)x.x, a1); a1 = __dp4a((int)v1.y, (int)x.y, a1);
        a1 = __dp4a((int)v1.z, (int)x.z, a1); a1 = __dp4a((int)v1.w, (int)x.w, a1);
        a2 = __dp4a((int)v2.x, (int)x.x, a2); a2 = __dp4a((int)v2.y, (int)x.y, a2);
        a2 = __dp4a((int)v2.z, (int)x.z, a2); a2 = __dp4a((int)v2.w, (int)x.w, a2);
    }
    r0 = wredi(a0); r1 = wredi(a1); r2 = wredi(a2);
}

// same but L1-cached (.ca) — C-group critical ih1 slice, L1-resident across steps
__device__ __forceinline__ void dot3q_l1(const uint4* __restrict__ q0,
                                         const uint4* __restrict__ q1,
                                         const uint4* __restrict__ q2,
                                         const uint4* __restrict__ xq, int lane,
                                         int& r0, int& r1, int& r2) {
    int a0 = 0, a1 = 0, a2 = 0;
    #pragma unroll
    for (int it = 0; it < 3; ++it) {
        uint4 x  = xq[it * 32 + lane];
        uint4 v0 = __ldg(q0 + it * 32 + lane);
        uint4 v1 = __ldg(q1 + it * 32 + lane);
        uint4 v2 = __ldg(q2 + it * 32 + lane);
        a0 = __dp4a((int)v0.x, (int)x.x, a0); a0 = __dp4a((int)v0.y, (int)x.y, a0);
        a0 = __dp4a((int)v0.z, (int)x.z, a0); a0 = __dp4a((int)v0.w, (int)x.w, a0);
        a1 = __dp4a((int)v1.x, (int)x.x, a1); a1 = __dp4a((int)v1.y, (int)x.y, a1);
        a1 = __dp4a((int)v1.z, (int)x.z, a1); a1 = __dp4a((int)v1.w, (int)x.w, a1);
        a2 = __dp4a((int)v2.x, (int)x.x, a2); a2 = __dp4a((int)v2.y, (int)x.y, a2);
        a2 = __dp4a((int)v2.z, (int)x.z, a2); a2 = __dp4a((int)v2.w, (int)x.w, a2);
    }
    r0 = wredi(a0); r1 = wredi(a1); r2 = wredi(a2);
}

__device__ __forceinline__ unsigned quant4(float4 g, float inv) {
    int q0 = __float2int_rn(g.x * inv), q1 = __float2int_rn(g.y * inv);
    int q2 = __float2int_rn(g.z * inv), q3 = __float2int_rn(g.w * inv);
    return (q0 & 255) | ((q1 & 255) << 8) | ((q2 & 255) << 16) | ((q3 & 255) << 24);
}

#define BARC() asm volatile("bar.sync 1, 512;" ::: "memory")
#define BARP() asm volatile("bar.sync 2, 512;" ::: "memory")
// split producer/consumer barriers: P arrives, C syncs (512 + 512 = 1024)
#define SYNC3()   asm volatile("bar.sync 3, 1024;" ::: "memory")
#define ARRIVE3() asm volatile("bar.arrive 3, 1024;" ::: "memory")
#define SYNC4()   asm volatile("bar.sync 4, 1024;" ::: "memory")
#define ARRIVE4() asm volatile("bar.arrive 4, 1024;" ::: "memory")

__device__ __forceinline__ void bar_arrive_leader() {
    asm volatile("red.release.gpu.global.add.u32 [%0], 1;" :: "l"(&g_count) : "memory");
}
__device__ __forceinline__ void bar_poll_leader(unsigned target) {
    unsigned v;
    do {
        asm volatile("ld.acquire.gpu.global.u32 %0, [%1];" : "=r"(v) : "l"(&g_count) : "memory");
    } while (v < target);
}

// ---------------- persistent main kernel ----------------------------------------------
__global__ void __launch_bounds__(NTHR, 1) lstm_main(
    const float* __restrict__ inputVecs,
    const float* __restrict__ h0in, const float* __restrict__ c0in,
    const float* __restrict__ bi0, const float* __restrict__ bh0,
    const float* __restrict__ bi1, const float* __restrict__ bh1,
    float* __restrict__ out) {
    __shared__ __align__(16) float sxx[256];       // [x(118)|flag|pad|y(128)]
    __shared__ __align__(16) unsigned sxq[QW];     // C quantized h0n (fixed scale 1/127)
    __shared__ __align__(16) unsigned spq[QW];     // P quant buffer
    __shared__ float sgmaxP[12];
    __shared__ float sh1[12];
    __shared__ float sgate[48], sg1[48];
    __shared__ float pArow[48], pBrow[48];
    __shared__ float bA[48], bB[48];

    const int tid = threadIdx.x, lane = tid & 31, bid = blockIdx.x;
    const bool isC = tid < 512;
    const int wid = tid >> 5;          // C: 0..15
    const int i0 = (wid & 15) * 3;
    const float QS = 1.f / 127.f;      // fixed h scale

    int grow[3];
    #pragma unroll
    for (int i = 0; i < 3; i++) {
        int idx = i0 + i;
        grow[i] = (idx / 12) * H + bid * 12 + (idx % 12);
    }

    float cA = 0.f, cB = 0.f;
    if (isC && wid == 0 && lane < 12) {
        int j = bid * 12 + lane;
        cA = c0in[j]; cB = c0in[H + j];
    }
    if (tid < 48) {
        int g = (tid / 12) * H + bid * 12 + (tid % 12);
        bA[tid] = bi0[g] + bh0[g];
        bB[tid] = bi1[g] + bh1[g];
    }
    // C prologue: sxx = [x(0) | flag=0 | pad 0 | y=0]
    if (isC && tid < 256) {
        float v = 0.f;
        if (tid < IN_DIM) v = __ldg(inputVecs + tid);
        sxx[tid] = v;
    }

    float scI[3];
    const uint4 *qI[3], *wx[3];
    if (isC) {
        #pragma unroll
        for (int i = 0; i < 3; i++) {
            scI[i] = __ldg(&g_sI1[grow[i]]) * QS;
            qI[i] = reinterpret_cast<const uint4*>(g_QI1 + (size_t)grow[i] * QW);
            wx[i] = reinterpret_cast<const uint4*>(g_WXp + (size_t)grow[i] * 128);
        }
    }
    float scH0[3], scH1[3];
    const uint4 *qH0[3], *qH1[3];
    if (!isC) {
        #pragma unroll
        for (int i = 0; i < 3; i++) {
            scH0[i] = __ldg(&g_sH0[grow[i]]);
            scH1[i] = __ldg(&g_sH1[grow[i]]);
            qH0[i] = reinterpret_cast<const uint4*>(g_QH0 + (size_t)grow[i] * QW);
            qH1[i] = reinterpret_cast<const uint4*>(g_QH1 + (size_t)grow[i] * QW);
        }
    }
    __syncthreads();

    // P prologue: initial hh partials from h0in (dynamic scale — h0in unbounded),
    // then arm the split barriers once (arrivals for C's t=0 SYNC4/SYNC3).
    if (!isC) {
        const int ptid = tid - 512;
        const int pw = wid & 15;
        #pragma unroll
        for (int half = 0; half < 2; half++) {
            float4 gv = make_float4(0.f, 0.f, 0.f, 0.f);
            if (ptid < 384) {
                gv = *reinterpret_cast<const float4*>(h0in + half * H + 4 * ptid);
                float m = fmaxf(fmaxf(fabsf(gv.x), fabsf(gv.y)), fmaxf(fabsf(gv.z), fabsf(gv.w)));
                #pragma unroll
                for (int o = 16; o; o >>= 1) m = fmaxf(m, __shfl_xor_sync(0xffffffffu, m, o));
                if (lane == 0 && pw < 12) sgmaxP[pw] = m;
            }
            BARP();
            float mx = 0.f;
            #pragma unroll
            for (int i = 0; i < 12; i++) mx = fmaxf(mx, sgmaxP[i]);
            float inv = (mx > 0.f) ? 127.f / mx : 0.f;
            float sxs = mx / 127.f;
            if (ptid < 384) spq[ptid] = quant4(gv, inv);
            BARP();
            int r0, r1, r2;
            if (half == 0) {
                dot3q_cg(qH0[0], qH0[1], qH0[2], reinterpret_cast<const uint4*>(spq), lane, r0, r1, r2);
                if (lane == 0) {
                    pArow[i0]     = (float)r0 * (scH0[0] * sxs);
                    pArow[i0 + 1] = (float)r1 * (scH0[1] * sxs);
                    pArow[i0 + 2] = (float)r2 * (scH0[2] * sxs);
                }
            } else {
                dot3q_cg(qH1[0], qH1[1], qH1[2], reinterpret_cast<const uint4*>(spq), lane, r0, r1, r2);
                if (lane == 0) {
                    pBrow[i0]     = (float)r0 * (scH1[0] * sxs);
                    pBrow[i0 + 1] = (float)r1 * (scH1[1] * sxs);
                    pBrow[i0 + 2] = (float)r2 * (scH1[2] * sxs);
                }
            }
            BARP();
        }
        ARRIVE4();   // pArow armed for C t=0
        ARRIVE3();   // pBrow armed for C t=0
    }

    if (isC) {
        // ============================ C-group loop ===================================
        unsigned ep1 = NBLK, ep2 = 2 * NBLK;
        for (int t = 0; t < T_STEPS; ++t) {
            const int par = t & 1;
            SYNC4();   // pArow ready (P arrival) + C-C: sxx (x prefetch + y) visible
            // ---- phase A: bf16 [x|flag|y] dot + pArow -> h0n (quant store) ----------
            {
                unsigned long long A0 = 0ull, A1 = 0ull, A2 = 0ull;
                ulonglong2 xa = *reinterpret_cast<const ulonglong2*>(sxx + lane * 8);
                ulonglong2 xb = *reinterpret_cast<const ulonglong2*>(sxx + lane * 8 + 4);
                uint4 v0 = __ldg(wx[0] + lane);
                uint4 v1 = __ldg(wx[1] + lane);
                uint4 v2 = __ldg(wx[2] + lane);
                bffma2p(A0, v0.x, xa.x); bffma2p(A0, v0.y, xa.y);
                bffma2p(A0, v0.z, xb.x); bffma2p(A0, v0.w, xb.y);
                bffma2p(A1, v1.x, xa.x); bffma2p(A1, v1.y, xa.y);
                bffma2p(A1, v1.z, xb.x); bffma2p(A1, v1.w, xb.y);
                bffma2p(A2, v2.x, xa.x); bffma2p(A2, v2.y, xa.y);
                bffma2p(A2, v2.z, xb.x); bffma2p(A2, v2.w, xb.y);
                float s0 = wred(upsum(A0)), s1 = wred(upsum(A1)), s2 = wred(upsum(A2));
                if (lane == 0) {
                    sgate[i0]     = s0 + pArow[i0]     + bA[i0];
                    sgate[i0 + 1] = s1 + pArow[i0 + 1] + bA[i0 + 1];
                    sgate[i0 + 2] = s2 + pArow[i0 + 2] + bA[i0 + 2];
                }
            }
            BARC();
            if (wid == 0) {
                unsigned bq = 0;
                if (lane < 12) {
                    float gi = sigf(sgate[lane]);
                    float gf = sigf(sgate[12 + lane]);
                    float gg = tanhf_fast(sgate[24 + lane]);
                    float go = sigf(sgate[36 + lane]);
                    cA = gf * cA + gi * gg;
                    float h = go * tanhf_fast(cA);
                    bq = (unsigned)__float2int_rn(h * 127.f) & 255u;
                }
                unsigned p0 = __shfl_sync(0xffffffffu, bq, (lane * 4) & 31);
                unsigned p1 = __shfl_sync(0xffffffffu, bq, (lane * 4 + 1) & 31);
                unsigned p2 = __shfl_sync(0xffffffffu, bq, (lane * 4 + 2) & 31);
                unsigned p3 = __shfl_sync(0xffffffffu, bq, (lane * 4 + 3) & 31);
                if (lane < 3)
                    g_h0q[bid * 3 + lane] = p0 | (p1 << 8) | (p2 << 16) | (p3 << 24);
                __syncwarp();
                if (lane == 0) { bar_arrive_leader(); bar_poll_leader(ep1); }   // bar1
            }
            BARC();     // all C released once warp0 passed bar1
            // ---- slot B: gather h0q; prefetch x(t+1); int8 ih1 dot + pBrow -> h1n ---
            if (tid < 96)
                reinterpret_cast<uint4*>(sxq)[tid] =
                    __ldcg(reinterpret_cast<const uint4*>(g_h0q) + tid);
            if (tid >= 128 && tid < 128 + IN_DIM + 1 && t + 1 < T_STEPS) {
                int j = tid - 128;
                sxx[j] = (j < IN_DIM) ? __ldg(inputVecs + (size_t)(t + 1) * IN_DIM + j) : 1.f;
            }
            SYNC3();   // sxq + x(t+1) visible + pBrow ready (P arrival)
            {
                int r0, r1, r2;
                dot3q_l1(qI[0], qI[1], qI[2], reinterpret_cast<const uint4*>(sxq), lane, r0, r1, r2);
                if (lane == 0) {
                    sg1[i0]     = (float)r0 * scI[0] + pBrow[i0]     + bB[i0];
                    sg1[i0 + 1] = (float)r1 * scI[1] + pBrow[i0 + 1] + bB[i0 + 1];
                    sg1[i0 + 2] = (float)r2 * scI[2] + pBrow[i0 + 2] + bB[i0 + 2];
                }
            }
            BARC();
            if (wid == 0) {
                unsigned bq = 0;
                if (lane < 12) {
                    float gi = sigf(sg1[lane]);
                    float gf = sigf(sg1[12 + lane]);
                    float gg = tanhf_fast(sg1[24 + lane]);
                    float go = sigf(sg1[36 + lane]);
                    cB = gf * cB + gi * gg;
                    float h1n = go * tanhf_fast(cB);
                    sh1[lane] = h1n;
                    bq = (unsigned)__float2int_rn(h1n * 127.f) & 255u;
                }
                unsigned p0 = __shfl_sync(0xffffffffu, bq, (lane * 4) & 31);
                unsigned p1 = __shfl_sync(0xffffffffu, bq, (lane * 4 + 1) & 31);
                unsigned p2 = __shfl_sync(0xffffffffu, bq, (lane * 4 + 2) & 31);
                unsigned p3 = __shfl_sync(0xffffffffu, bq, (lane * 4 + 3) & 31);
                if (lane < 3)
                    g_h1q[bid * 3 + lane] = p0 | (p1 << 8) | (p2 << 16) | (p3 << 24);
            }
            BARC();     // sh1 + h1q visible
            if (tid < OUTD) {   // rank-12 logit contribution
                const float* wc = g_WCBT + (size_t)(bid * 12) * OUTD + tid;
                float p = 0.f;
                #pragma unroll
                for (int i = 0; i < 12; i++) p = fmaf(__ldg(wc + i * OUTD), sh1[i], p);
                asm volatile("red.relaxed.gpu.global.add.f32 [%0], %1;"
                             :: "l"(&g_L[par][tid]), "f"(p) : "memory");
            }
            BARC();
            if (tid == 0) { bar_arrive_leader(); bar_poll_leader(ep2); }   // bar2
            BARC();
            // ---- slot4 (block-local): softmax -> y into sxx[128..255] ---------------
            if (tid == 256) g_L[par ^ 1][bid] = __ldg(&g_bcomb[bid]);   // reset for t+2
            if (wid == 0) {
                float v0 = __ldcg(&g_L[par][lane]);
                float v1 = __ldcg(&g_L[par][lane + 32]);
                float v2 = __ldcg(&g_L[par][lane + 64]);
                float v3 = __ldcg(&g_L[par][lane + 96]);
                float m = fmaxf(fmaxf(v0, v1), fmaxf(v2, v3));
                #pragma unroll
                for (int o = 16; o; o >>= 1) m = fmaxf(m, __shfl_xor_sync(0xffffffffu, m, o));
                float e0 = __expf(v0 - m), e1 = __expf(v1 - m);
                float e2 = __expf(v2 - m), e3 = __expf(v3 - m);
                float s = wred(e0 + e1 + e2 + e3);
                float is = __fdividef(1.f, s);
                e0 *= is; e1 *= is; e2 *= is; e3 *= is;
                sxx[128 + lane] = e0; sxx[160 + lane] = e1;
                sxx[192 + lane] = e2; sxx[224 + lane] = e3;
                if (bid == 0) {
                    float* op = out + (size_t)t * OUTD;
                    op[lane] = e0; op[lane + 32] = e1; op[lane + 64] = e2; op[lane + 96] = e3;
                }
            }
            // next iteration's SYNC4 provides the C-C visibility barrier for sxx
            ep1 += 2 * NBLK; ep2 += 2 * NBLK;
        }
    } else {
        // ============================ P-group loop ===================================
        // Iteration t prepares partials for step t+1; final iteration skipped.
        const int ptid = tid - 512;
        unsigned ep1 = NBLK, ep2 = 2 * NBLK;
        for (int t = 0; t < T_STEPS - 1; ++t) {
            if (ptid == 0) bar_poll_leader(ep1);
            BARP();
            if (ptid < 96)
                reinterpret_cast<uint4*>(spq)[ptid] =
                    __ldcg(reinterpret_cast<const uint4*>(g_h0q) + ptid);
            BARP();
            {
                int r0, r1, r2;
                dot3q_cg(qH0[0], qH0[1], qH0[2], reinterpret_cast<const uint4*>(spq), lane, r0, r1, r2);
                if (lane == 0) {
                    pArow[i0]     = (float)r0 * (scH0[0] * QS);
                    pArow[i0 + 1] = (float)r1 * (scH0[1] * QS);
                    pArow[i0 + 2] = (float)r2 * (scH0[2] * QS);
                }
            }
            ARRIVE4();   // pArow(t+1) ready for C's phase A
            if (ptid == 0) bar_poll_leader(ep2);
            BARP();
            if (ptid < 96)
                reinterpret_cast<uint4*>(spq)[ptid] =
                    __ldcg(reinterpret_cast<const uint4*>(g_h1q) + ptid);
            BARP();
            {
                int r0, r1, r2;
                dot3q_cg(qH1[0], qH1[1], qH1[2], reinterpret_cast<const uint4*>(spq), lane, r0, r1, r2);
                if (lane == 0) {
                    pBrow[i0]     = (float)r0 * (scH1[0] * QS);
                    pBrow[i0 + 1] = (float)r1 * (scH1[1] * QS);
                    pBrow[i0 + 2] = (float)r2 * (scH1[2] * QS);
                }
            }
            ARRIVE3();   // pBrow(t+1) ready for C's slot B
            ep1 += 2 * NBLK; ep2 += 2 * NBLK;
        }
    }

    // end-of-launch reset (last arriver) for graph replay
    __syncthreads();
    if (tid == 0) {
        __threadfence();
        if (atomicAdd(&g_done, 1u) == NBLK - 1) {
            g_count = 0u;
            g_done = 0u;
            __threadfence();
        }
    }
}

// ---------------- launch --------------------------------------------------------------
extern "C" void kernel_launch(void* const* d_in, const int* in_sizes, int n_in,
                              void* d_out, int out_size) {
    const float* inputVecs = (const float*)d_in[0];
    const float* h0    = (const float*)d_in[1];
    const float* c0    = (const float*)d_in[2];
    const float* W_ih0 = (const float*)d_in[3];
    const float* W_hh0 = (const float*)d_in[4];
    const float* b_ih0 = (const float*)d_in[5];
    const float* b_hh0 = (const float*)d_in[6];
    const float* W_ih1 = (const float*)d_in[7];
    const float* W_hh1 = (const float*)d_in[8];
    const float* b_ih1 = (const float*)d_in[9];
    const float* b_hh1 = (const float*)d_in[10];
    const float* W_hl  = (const float*)d_in[11];
    const float* b_hl  = (const float*)d_in[12];
    const float* W_out = (const float*)d_in[13];
    const float* b_out = (const float*)d_in[14];
    const float* W_map = (const float*)d_in[15];
    const float* b_map = (const float*)d_in[16];

    pack_quant<<<(3 * H4 + 7) / 8, 256>>>(W_ih1, W_hh0, W_hh1);
    pack_rest<<<1024, 256>>>(W_ih0, W_hl, W_out, b_hl, b_out, W_map, b_map);
    lstm_main<<<NBLK, NTHR>>>(inputVecs, h0, c0,
                              b_ih0, b_hh0, b_ih1, b_hh1,
                              (float*)d_out);
}